// round 1
// baseline (speedup 1.0000x reference)
#include <cuda_runtime.h>
#include <cuda_bf16.h>
#include <math.h>

// Problem constants
#define NB   16      // batch
#define CC   256     // Cout
#define CIN  192
#define CE   768
#define HH   32
#define WW   32
#define SS   1024    // H*W
#define NHEAD 4
#define CPH  64

#define EPSV 1e-4f
#define SILU_SCALE 1.6778523489932886f   // 1/0.596
#define CA 0.9191450300180579f           // 0.7/sqrt(0.58)
#define CB 0.3939192985791677f           // 0.3/sqrt(0.58)

// ---------------- scratch (static device memory; no allocs) ----------------
__device__ float g_wskip[CC * CIN];
__device__ float g_wres0[CC * CC * 9];
__device__ float g_wres1[CC * CC * 9];
__device__ float g_wemb[CC * CE];
__device__ float g_wqkv[3 * CC * CC];
__device__ float g_wproj[CC * CC];
__device__ float g_c[NB * CC];
__device__ float g_x[NB * CC * SS];
__device__ float g_y[NB * CC * SS];
__device__ float g_qkv[NB * 3 * CC * SS];
__device__ float g_q[NB * NHEAD * CPH * SS];
__device__ float g_k[NB * NHEAD * CPH * SS];
__device__ float g_v[NB * NHEAD * CPH * SS];
__device__ float g_ao[NB * CC * SS];

__device__ __forceinline__ float mp_silu(float v) {
    return v / (1.f + __expf(-v)) * SILU_SCALE;
}

// ---------------- weight normalization: per-output-row ----------------
__global__ void k_wnorm(const float* __restrict__ w, float* __restrict__ out,
                        int fanin, const float* __restrict__ gain_ptr) {
    int o = blockIdx.x;
    const float* row = w + (long)o * fanin;
    float s = 0.f;
    for (int i = threadIdx.x; i < fanin; i += blockDim.x) { float v = row[i]; s += v * v; }
    __shared__ float red[256];
    red[threadIdx.x] = s;
    __syncthreads();
    for (int off = 128; off > 0; off >>= 1) {
        if (threadIdx.x < off) red[threadIdx.x] += red[threadIdx.x + off];
        __syncthreads();
    }
    float nrm = sqrtf(red[0]);
    float g = gain_ptr ? *gain_ptr : 1.0f;
    float sf = sqrtf((float)fanin);
    float scale = g / (sf * (EPSV + nrm / sf));
    for (int i = threadIdx.x; i < fanin; i += blockDim.x)
        out[(long)o * fanin + i] = row[i] * scale;
}

// ---------------- emb modulation: c = emb @ w_emb^T + 1 ----------------
__global__ void k_emb(const float* __restrict__ emb) {
    int n = blockIdx.x, co = threadIdx.x;
    const float* e = emb + n * CE;
    const float* wr = g_wemb + (long)co * CE;
    float a = 0.f;
    for (int k = 0; k < CE; k++) a += e[k] * wr[k];
    g_c[n * CC + co] = a + 1.0f;
}

// ---------------- 1x1 conv as GEMM (128 px x 64 co per block) ----------------
// mode 0: plain write. mode 1: out = clip(CA*res + CB*acc) (final proj epilogue)
__global__ __launch_bounds__(256) void k_conv1x1(
    const float* __restrict__ in, const float* __restrict__ w,
    float* __restrict__ out, int cin, int cout, int mode,
    const float* __restrict__ res) {
    int n = blockIdx.z;
    int p0 = blockIdx.x * 128;
    int co0 = blockIdx.y * 64;
    int tid = threadIdx.x;
    int pg = tid & 31;       // 4 px each
    int cg = tid >> 5;       // 8 co each
    __shared__ __align__(16) float sIn[8][128];
    __shared__ __align__(16) float sW[8][64];
    float acc[8][4] = {};
    const float* inb = in + (long)n * cin * SS + p0;
    for (int c0 = 0; c0 < cin; c0 += 8) {
        for (int t = tid; t < 1024; t += 256) {
            int r = t >> 7, c = t & 127;
            sIn[r][c] = inb[(long)(c0 + r) * SS + c];
        }
        for (int t = tid; t < 512; t += 256) {
            int r = t >> 6, c = t & 63;
            sW[r][c] = w[(long)(co0 + c) * cin + c0 + r];
        }
        __syncthreads();
#pragma unroll
        for (int r = 0; r < 8; r++) {
            float4 a4 = *(const float4*)&sIn[r][pg * 4];
            float4 b0 = *(const float4*)&sW[r][cg * 8];
            float4 b1 = *(const float4*)&sW[r][cg * 8 + 4];
            float av[4] = {a4.x, a4.y, a4.z, a4.w};
            float bv[8] = {b0.x, b0.y, b0.z, b0.w, b1.x, b1.y, b1.z, b1.w};
#pragma unroll
            for (int j = 0; j < 8; j++)
#pragma unroll
                for (int i = 0; i < 4; i++)
                    acc[j][i] += bv[j] * av[i];
        }
        __syncthreads();
    }
#pragma unroll
    for (int j = 0; j < 8; j++) {
        int co = co0 + cg * 8 + j;
        long base = ((long)n * cout + co) * SS + p0 + pg * 4;
#pragma unroll
        for (int i = 0; i < 4; i++) {
            float v = acc[j][i];
            if (mode == 1) {
                v = CA * res[base + i] + CB * v;
                v = fminf(fmaxf(v, -256.f), 256.f);
            }
            out[base + i] = v;
        }
    }
}

// ---------------- pixel norm across 256 channels ----------------
__global__ __launch_bounds__(256) void k_pixnorm(float* __restrict__ x) {
    int blk = blockIdx.x;            // NB * (SS/32) blocks
    int n = blk >> 5;
    int s0 = (blk & 31) * 32;
    int px = threadIdx.x & 31, cg = threadIdx.x >> 5;
    long base = (long)n * CC * SS + s0 + px;
    float vals[32];
    float s2 = 0.f;
#pragma unroll
    for (int i = 0; i < 32; i++) {
        float v = x[base + (long)(cg * 32 + i) * SS];
        vals[i] = v;
        s2 += v * v;
    }
    __shared__ float red[8][32];
    red[cg][px] = s2;
    __syncthreads();
    float tot = 0.f;
#pragma unroll
    for (int g = 0; g < 8; g++) tot += red[g][px];
    float scale = 1.f / (EPSV + sqrtf(tot) * 0.0625f);
#pragma unroll
    for (int i = 0; i < 32; i++)
        x[base + (long)(cg * 32 + i) * SS] = vals[i] * scale;
}

// ---------------- 3x3 conv, register tiled. silu fused on input load.
// mode 0: out = conv * c[n][co]     (res0)
// mode 1: out = CA*res + CB*conv    (res1 + mp_sum into x)
__global__ __launch_bounds__(256) void k_conv3x3(
    const float* __restrict__ in, const float* __restrict__ w,
    float* __restrict__ out, int mode, const float* __restrict__ res) {
    int co0 = blockIdx.x * 32, h0 = blockIdx.y * 8, n = blockIdx.z;
    int tid = threadIdx.x;
    int pxg = tid & 7;           // 4 px each -> 32 wide
    int hy = (tid >> 3) & 7;     // 8 rows
    int cog = tid >> 6;          // 4 groups of 8 co
    __shared__ float sIn[2][10][34];
    __shared__ float sW[2][32][9];
    float acc[8][4] = {};
    for (int c0 = 0; c0 < CC; c0 += 2) {
        for (int t = tid; t < 680; t += 256) {
            int cc = t / 340;
            int rem = t - cc * 340;
            int r = rem / 34;
            int col = rem - r * 34;
            int hr = h0 + r - 1, wc = col - 1;
            float v = 0.f;
            if ((unsigned)hr < 32u && (unsigned)wc < 32u)
                v = mp_silu(in[(((long)n * CC + c0 + cc) * HH + hr) * WW + wc]);
            else
                v = 0.f;
            sIn[cc][r][col] = v;
        }
        for (int t = tid; t < 576; t += 256) {
            int cc = t / 288;
            int rem = t - cc * 288;
            int co = rem / 9;
            int k = rem - co * 9;
            sW[cc][co][k] = w[((long)(co0 + co) * CC + c0 + cc) * 9 + k];
        }
        __syncthreads();
#pragma unroll
        for (int cc = 0; cc < 2; cc++) {
            float v[3][6];
#pragma unroll
            for (int dy = 0; dy < 3; dy++)
#pragma unroll
                for (int j = 0; j < 6; j++)
                    v[dy][j] = sIn[cc][hy + dy][pxg * 4 + j];
#pragma unroll
            for (int co = 0; co < 8; co++) {
                float w9[9];
#pragma unroll
                for (int k = 0; k < 9; k++) w9[k] = sW[cc][cog * 8 + co][k];
#pragma unroll
                for (int i = 0; i < 4; i++) {
                    float s = acc[co][i];
#pragma unroll
                    for (int dy = 0; dy < 3; dy++)
#pragma unroll
                        for (int dx = 0; dx < 3; dx++)
                            s += v[dy][i + dx] * w9[dy * 3 + dx];
                    acc[co][i] = s;
                }
            }
        }
        __syncthreads();
    }
    int hr = h0 + hy;
#pragma unroll
    for (int co = 0; co < 8; co++) {
        int gco = co0 + cog * 8 + co;
        long base = (((long)n * CC + gco) * HH + hr) * WW + pxg * 4;
        if (mode == 0) {
            float cm = g_c[n * CC + gco];
#pragma unroll
            for (int i = 0; i < 4; i++) out[base + i] = acc[co][i] * cm;
        } else {
#pragma unroll
            for (int i = 0; i < 4; i++)
                out[base + i] = CA * res[base + i] + CB * acc[co][i];
        }
    }
}

// ---------------- qkv normalize + transpose to (N,H,C,S) ----------------
__global__ __launch_bounds__(256) void k_qkvnorm() {
    int stile = blockIdx.x;         // 32 tiles of 32
    int which = blockIdx.y;         // 0=q 1=k 2=v
    int nh = blockIdx.z;            // n*4+h
    int n = nh >> 2, h = nh & 3;
    int px = threadIdx.x & 31, cg = threadIdx.x >> 5;
    int s = stile * 32 + px;
    float vals[8];
    float s2 = 0.f;
#pragma unroll
    for (int i = 0; i < 8; i++) {
        int cph = cg * 8 + i;
        int ch = h * 192 + cph * 3 + which;
        float v = g_qkv[((long)n * (3 * CC) + ch) * SS + s];
        vals[i] = v;
        s2 += v * v;
    }
    __shared__ float red[8][32];
    red[cg][px] = s2;
    __syncthreads();
    float tot = 0.f;
#pragma unroll
    for (int g = 0; g < 8; g++) tot += red[g][px];
    float scale = 1.f / (EPSV + sqrtf(tot) * 0.125f);
    float* dst = (which == 0) ? g_q : (which == 1) ? g_k : g_v;
#pragma unroll
    for (int i = 0; i < 8; i++)
        dst[((long)nh * CPH + cg * 8 + i) * SS + s] = vals[i] * scale;
}

// ---------------- attention: flash-style, thread per query ----------------
__global__ __launch_bounds__(128) void k_attn() {
    int nh = blockIdx.y;
    int s = blockIdx.x * 128 + threadIdx.x;
    long off = (long)nh * CPH * SS;
    const float* qp = g_q + off;
    const float* kp = g_k + off;
    const float* vp = g_v + off;
    float q[64];
#pragma unroll
    for (int c = 0; c < 64; c++) q[c] = qp[(long)c * SS + s];
    float m = -1e30f, l = 0.f;
    float acc[64] = {};
    __shared__ float sK[16][65];
    __shared__ float sV[16][65];
    for (int k0 = 0; k0 < SS; k0 += 16) {
        for (int t = threadIdx.x; t < 1024; t += 128) {
            int c = t >> 4, j = t & 15;
            sK[j][c] = kp[(long)c * SS + k0 + j];
            sV[j][c] = vp[(long)c * SS + k0 + j];
        }
        __syncthreads();
        float sc[16];
        float tmax = -1e30f;
#pragma unroll
        for (int j = 0; j < 16; j++) {
            float d = 0.f;
#pragma unroll
            for (int c = 0; c < 64; c++) d += q[c] * sK[j][c];
            d *= 0.125f;
            sc[j] = d;
            tmax = fmaxf(tmax, d);
        }
        float mn = fmaxf(m, tmax);
        float corr = __expf(m - mn);
        l *= corr;
#pragma unroll
        for (int c = 0; c < 64; c++) acc[c] *= corr;
#pragma unroll
        for (int j = 0; j < 16; j++) {
            float p = __expf(sc[j] - mn);
            l += p;
#pragma unroll
            for (int c = 0; c < 64; c++) acc[c] += p * sV[j][c];
        }
        m = mn;
        __syncthreads();
    }
    float inv = 1.f / l;
#pragma unroll
    for (int c = 0; c < 64; c++)
        g_ao[((long)nh * CPH + c) * SS + s] = acc[c] * inv;
}

// ---------------- launcher ----------------
extern "C" void kernel_launch(void* const* d_in, const int* in_sizes, int n_in,
                              void* d_out, int out_size) {
    const float* x       = (const float*)d_in[0];
    const float* emb     = (const float*)d_in[1];
    const float* w_skip  = (const float*)d_in[2];
    const float* w_res0  = (const float*)d_in[3];
    const float* w_res1  = (const float*)d_in[4];
    const float* w_emb   = (const float*)d_in[5];
    const float* emb_g   = (const float*)d_in[6];
    const float* w_qkv   = (const float*)d_in[7];
    const float* w_proj  = (const float*)d_in[8];
    float* out = (float*)d_out;

    float *p_wskip, *p_wres0, *p_wres1, *p_wemb, *p_wqkv, *p_wproj;
    float *p_x, *p_y, *p_qkv, *p_ao;
    cudaGetSymbolAddress((void**)&p_wskip, g_wskip);
    cudaGetSymbolAddress((void**)&p_wres0, g_wres0);
    cudaGetSymbolAddress((void**)&p_wres1, g_wres1);
    cudaGetSymbolAddress((void**)&p_wemb,  g_wemb);
    cudaGetSymbolAddress((void**)&p_wqkv,  g_wqkv);
    cudaGetSymbolAddress((void**)&p_wproj, g_wproj);
    cudaGetSymbolAddress((void**)&p_x,   g_x);
    cudaGetSymbolAddress((void**)&p_y,   g_y);
    cudaGetSymbolAddress((void**)&p_qkv, g_qkv);
    cudaGetSymbolAddress((void**)&p_ao,  g_ao);

    // weight normalization
    k_wnorm<<<CC, 256>>>(w_skip, p_wskip, CIN, nullptr);
    k_wnorm<<<CC, 256>>>(w_res0, p_wres0, CC * 9, nullptr);
    k_wnorm<<<CC, 256>>>(w_res1, p_wres1, CC * 9, nullptr);
    k_wnorm<<<CC, 256>>>(w_emb,  p_wemb,  CE, emb_g);
    k_wnorm<<<3 * CC, 256>>>(w_qkv, p_wqkv, CC, nullptr);
    k_wnorm<<<CC, 256>>>(w_proj, p_wproj, CC, nullptr);

    // emb modulation vector
    k_emb<<<NB, 256>>>(emb);

    // skip conv (192 -> 256) then pixel norm (in place)
    k_conv1x1<<<dim3(SS / 128, CC / 64, NB), 256>>>(x, p_wskip, p_x, CIN, CC, 0, nullptr);
    k_pixnorm<<<NB * (SS / 32), 256>>>(p_x);

    // res conv 0: y = conv3x3(silu(x)) * c
    k_conv3x3<<<dim3(CC / 32, HH / 8, NB), 256>>>(p_x, p_wres0, p_y, 0, nullptr);
    // res conv 1: x = mp_sum(x, conv3x3(silu(y)), 0.3)
    k_conv3x3<<<dim3(CC / 32, HH / 8, NB), 256>>>(p_y, p_wres1, p_x, 1, p_x);

    // qkv conv (256 -> 768)
    k_conv1x1<<<dim3(SS / 128, (3 * CC) / 64, NB), 256>>>(p_x, p_wqkv, p_qkv, CC, 3 * CC, 0, nullptr);
    // normalize + transpose into q/k/v (N,H,C,S)
    k_qkvnorm<<<dim3(SS / 32, 3, NB * NHEAD), 256>>>();
    // attention
    k_attn<<<dim3(SS / 128, NB * NHEAD), 128>>>();

    // proj conv + mp_sum + clip -> d_out
    k_conv1x1<<<dim3(SS / 128, CC / 64, NB), 256>>>(p_ao, p_wproj, out, CC, CC, 1, p_x);
}

// round 3
// speedup vs baseline: 2.1860x; 2.1860x over previous
#include <cuda_runtime.h>
#include <cuda_bf16.h>
#include <math.h>
#include <stdint.h>

#define NB   16
#define CC   256
#define CIN  192
#define CE   768
#define HH   32
#define WW   32
#define SS   1024
#define NHEAD 4
#define CPH  64

#define EPSV 1e-4f
#define SILU_SCALE 1.6778523489932886f   // 1/0.596
#define CA 0.9191450300180579f           // 0.7/sqrt(0.58)
#define CB 0.3939192985791677f           // 0.3/sqrt(0.58)

typedef __nv_bfloat16 bf16;

// ---------------- static device scratch ----------------
__device__ bf16 g_hA[NB * SS * CC];
__device__ bf16 g_lA[NB * SS * CC];
__device__ bf16 g_hB[NB * SS * CC];
__device__ bf16 g_lB[NB * SS * CC];
__device__ bf16 g_wh_skip[CC * CIN],    g_wl_skip[CC * CIN];
__device__ bf16 g_wh_res0[CC * CC * 9], g_wl_res0[CC * CC * 9];
__device__ bf16 g_wh_res1[CC * CC * 9], g_wl_res1[CC * CC * 9];
__device__ bf16 g_wh_qkv[3 * CC * CC],  g_wl_qkv[3 * CC * CC];
__device__ bf16 g_wh_proj[CC * CC],     g_wl_proj[CC * CC];
__device__ float g_wemb[CC * CE];
__device__ float g_c[NB * CC];
__device__ float g_x[NB * SS * CC];        // channel-last fp32
__device__ float g_y[NB * SS * CC];        // channel-last fp32
__device__ float g_qkvf[NB * SS * 3 * CC]; // channel-last fp32
__device__ float g_q[NB * NHEAD * CPH * SS];
__device__ float g_k[NB * NHEAD * CPH * SS];
__device__ float g_v[NB * NHEAD * CPH * SS];

__device__ __forceinline__ float mp_silu(float v) {
    return v / (1.f + __expf(-v)) * SILU_SCALE;
}
__device__ __forceinline__ void split2(float v, bf16& h, bf16& l) {
    h = __float2bfloat16(v);
    l = __float2bfloat16(v - __bfloat162float(h));
}
__device__ __forceinline__ uint32_t pack2(bf16 a, bf16 b) {
    return (uint32_t)__bfloat16_as_ushort(a) | ((uint32_t)__bfloat16_as_ushort(b) << 16);
}
__device__ __forceinline__ uint32_t smem_u32(const void* p) {
    uint32_t a;
    asm("{ .reg .u64 t; cvta.to.shared.u64 t, %1; cvt.u32.u64 %0, t; }" : "=r"(a) : "l"(p));
    return a;
}
__device__ __forceinline__ void cpa16(uint32_t d, const void* s, int sz) {
    asm volatile("cp.async.cg.shared.global [%0], [%1], 16, %2;"
                 :: "r"(d), "l"(s), "r"(sz));
}
__device__ __forceinline__ void ldsm4(uint32_t* r, uint32_t addr) {
    asm volatile("ldmatrix.sync.aligned.m8n8.x4.shared.b16 {%0,%1,%2,%3}, [%4];"
                 : "=r"(r[0]), "=r"(r[1]), "=r"(r[2]), "=r"(r[3]) : "r"(addr));
}
__device__ __forceinline__ void mma16816(float* c, const uint32_t* a, const uint32_t* b) {
    asm volatile(
        "mma.sync.aligned.m16n8k16.row.col.f32.bf16.bf16.f32 "
        "{%0,%1,%2,%3}, {%4,%5,%6,%7}, {%8,%9}, {%0,%1,%2,%3};"
        : "+f"(c[0]), "+f"(c[1]), "+f"(c[2]), "+f"(c[3])
        : "r"(a[0]), "r"(a[1]), "r"(a[2]), "r"(a[3]), "r"(b[0]), "r"(b[1]));
}

// ---------------- weight prep: normalize + split + tap-major relayout -------
__global__ void k_wprep(const float* __restrict__ w, bf16* __restrict__ oh,
                        bf16* __restrict__ ol, int cin, int taps) {
    int o = blockIdx.x;
    int fan = cin * taps;
    const float* row = w + (long)o * fan;
    float s = 0.f;
    for (int i = threadIdx.x; i < fan; i += 256) { float v = row[i]; s += v * v; }
    __shared__ float red[256];
    red[threadIdx.x] = s;
    __syncthreads();
    for (int off = 128; off > 0; off >>= 1) {
        if (threadIdx.x < off) red[threadIdx.x] += red[threadIdx.x + off];
        __syncthreads();
    }
    float sf = sqrtf((float)fan);
    float scale = 1.f / (sf * (EPSV + sqrtf(red[0]) / sf));
    for (int i = threadIdx.x; i < fan; i += 256) {
        int ci = i / taps, tap = i - ci * taps;  // input [ci][tap]
        bf16 h, l;
        split2(row[i] * scale, h, l);
        long oi = (long)o * fan + tap * cin + ci;
        oh[oi] = h;
        ol[oi] = l;
    }
}

__global__ void k_wnorm(const float* __restrict__ w, float* __restrict__ out,
                        int fanin, const float* __restrict__ gain_ptr) {
    int o = blockIdx.x;
    const float* row = w + (long)o * fanin;
    float s = 0.f;
    for (int i = threadIdx.x; i < fanin; i += 256) { float v = row[i]; s += v * v; }
    __shared__ float red[256];
    red[threadIdx.x] = s;
    __syncthreads();
    for (int off = 128; off > 0; off >>= 1) {
        if (threadIdx.x < off) red[threadIdx.x] += red[threadIdx.x + off];
        __syncthreads();
    }
    float g = gain_ptr ? *gain_ptr : 1.0f;
    float sf = sqrtf((float)fanin);
    float scale = g / (sf * (EPSV + sqrtf(red[0]) / sf));
    for (int i = threadIdx.x; i < fanin; i += 256)
        out[(long)o * fanin + i] = row[i] * scale;
}

__global__ void k_emb(const float* __restrict__ emb) {
    int n = blockIdx.x, co = threadIdx.x;
    const float* e = emb + n * CE;
    const float* wr = g_wemb + (long)co * CE;
    float a = 0.f;
    for (int k = 0; k < CE; k++) a += e[k] * wr[k];
    g_c[n * CC + co] = a + 1.0f;
}

// ---------------- input NCHW (192ch) -> channel-last hi/lo ----------------
__global__ __launch_bounds__(256) void k_split0(const float* __restrict__ in) {
    __shared__ float t[32][33];
    int s0 = blockIdx.x * 32, c0 = blockIdx.y * 32, n = blockIdx.z;
    int li = threadIdx.x & 31, gi = threadIdx.x >> 5;
#pragma unroll
    for (int it = 0; it < 4; it++) {
        int c = gi + it * 8;
        t[c][li] = in[((long)n * CIN + c0 + c) * SS + s0 + li];
    }
    __syncthreads();
#pragma unroll
    for (int it = 0; it < 4; it++) {
        int s = gi + it * 8;
        float v = t[li][s];
        bf16 h, l;
        split2(v, h, l);
        long oi = ((long)n * SS + s0 + s) * CIN + c0 + li;
        g_hA[oi] = h;
        g_lA[oi] = l;
    }
}

// ---------------- generic channel-last split (optional silu) ----------------
__global__ void k_split(const float* __restrict__ in, bf16* __restrict__ hi,
                        bf16* __restrict__ lo, int dosilu) {
    long i = ((long)blockIdx.x * 256 + threadIdx.x) * 4;
    float4 v = *(const float4*)(in + i);
    if (dosilu) { v.x = mp_silu(v.x); v.y = mp_silu(v.y); v.z = mp_silu(v.z); v.w = mp_silu(v.w); }
    bf16 h0, l0, h1, l1, h2, l2, h3, l3;
    split2(v.x, h0, l0); split2(v.y, h1, l1); split2(v.z, h2, l2); split2(v.w, h3, l3);
    uint2 ph = make_uint2(pack2(h0, h1), pack2(h2, h3));
    uint2 pl = make_uint2(pack2(l0, l1), pack2(l2, l3));
    *(uint2*)(hi + i) = ph;
    *(uint2*)(lo + i) = pl;
}

// ---------------- pixel norm (channel-last, warp per pixel) + silu-split ----
__global__ __launch_bounds__(256) void k_pixnorm(float* __restrict__ x) {
    int row = blockIdx.x * 8 + (threadIdx.x >> 5);   // global (n,s) row
    int lane = threadIdx.x & 31;
    long base = (long)row * CC + lane * 8;
    float4 a = *(const float4*)(x + base);
    float4 b = *(const float4*)(x + base + 4);
    float s = a.x * a.x + a.y * a.y + a.z * a.z + a.w * a.w
            + b.x * b.x + b.y * b.y + b.z * b.z + b.w * b.w;
#pragma unroll
    for (int o = 16; o > 0; o >>= 1) s += __shfl_xor_sync(0xffffffffu, s, o);
    float scale = 1.f / (EPSV + sqrtf(s) * 0.0625f);
    float v[8] = {a.x, a.y, a.z, a.w, b.x, b.y, b.z, b.w};
    bf16 h[8], l[8];
#pragma unroll
    for (int i = 0; i < 8; i++) {
        v[i] *= scale;
        split2(mp_silu(v[i]), h[i], l[i]);
    }
    *(float4*)(x + base) = make_float4(v[0], v[1], v[2], v[3]);
    *(float4*)(x + base + 4) = make_float4(v[4], v[5], v[6], v[7]);
    uint4 ph = make_uint4(pack2(h[0], h[1]), pack2(h[2], h[3]), pack2(h[4], h[5]), pack2(h[6], h[7]));
    uint4 pl = make_uint4(pack2(l[0], l[1]), pack2(l[2], l[3]), pack2(l[4], l[5]), pack2(l[6], l[7]));
    *(uint4*)(g_hA + base) = ph;
    *(uint4*)(g_lA + base) = pl;
}

// ---------------- mma.sync GEMM / implicit conv ----------------
// D[co,px] += A[co,k]*B[px,k], K = taps*cin. bf16 hi/lo, 3-pass.
// modes: 0 plain fp32 channel-last; 1 *c; 2 CA*res+CB*acc; 4 CA*res+CB*acc+clip -> NCHW
#define GSMEM 81920
__global__ __launch_bounds__(256) void k_gemm(
    const bf16* __restrict__ inH, const bf16* __restrict__ inL,
    const bf16* __restrict__ wH, const bf16* __restrict__ wL,
    float* __restrict__ outF, const float* __restrict__ res,
    const float* __restrict__ cvec, int cin, int cout, int taps, int mode) {
    extern __shared__ char smem[];
    const int tid = threadIdx.x, lane = tid & 31, wid = tid >> 5;
    const int n = blockIdx.z, co0 = blockIdx.y * 128, pxb = blockIdx.x * 128;
    const int wco = wid >> 2, wpx = wid & 3;
    const int cpt = cin >> 5;
    const int nch = taps * cpt;
    const long Ktot = (long)taps * cin;
    const uint32_t sbase = smem_u32(smem);

    float acc[64];
#pragma unroll
    for (int i = 0; i < 64; i++) acc[i] = 0.f;

    // ---- chunk loader (cp.async) ----
    auto load_chunk = [&](int c, int buf) {
        int tap = c / cpt;
        int ci0 = (c - tap * cpt) << 5;
        int dy = (taps == 9) ? tap / 3 - 1 : 0;
        int dx = (taps == 9) ? tap % 3 - 1 : 0;
        uint32_t b = sbase + buf * 40960;
#pragma unroll
        for (int rep = 0; rep < 2; rep++) {
            int idx = tid + rep * 256;
            int r = idx >> 2, seg = idx & 3;
            uint32_t dA = b + r * 80 + seg * 16;
            long aoff = (long)(co0 + r) * Ktot + c * 32 + seg * 8;
            cpa16(dA, wH + aoff, 16);
            cpa16(dA + 10240, wL + aoff, 16);
        }
#pragma unroll
        for (int rep = 0; rep < 2; rep++) {
            int idx = tid + rep * 256;
            int p = idx >> 2, seg = idx & 3;
            int s = pxb + p;
            int hh = (s >> 5) + dy, ww = (s & 31) + dx;
            int valid = ((unsigned)hh < 32u) && ((unsigned)ww < 32u);
            long soff = ((long)n * SS + (valid ? hh * 32 + ww : 0)) * cin + ci0 + seg * 8;
            uint32_t dB = b + 20480 + p * 80 + seg * 16;
            int sz = valid ? 16 : 0;
            cpa16(dB, inH + soff, sz);
            cpa16(dB + 10240, inL + soff, sz);
        }
        asm volatile("cp.async.commit_group;" ::: "memory");
    };

    load_chunk(0, 0);
    for (int c = 0; c < nch; c++) {
        int buf = c & 1;
        if (c + 1 < nch) {
            load_chunk(c + 1, buf ^ 1);
            asm volatile("cp.async.wait_group 1;" ::: "memory");
        } else {
            asm volatile("cp.async.wait_group 0;" ::: "memory");
        }
        __syncthreads();
        uint32_t b = sbase + buf * 40960;
#pragma unroll
        for (int k16 = 0; k16 < 2; k16++) {
            uint32_t Bh[8], Bl[8];
#pragma unroll
            for (int t = 0; t < 2; t++) {
                int sub = lane >> 3, r7 = lane & 7;
                uint32_t prow = wpx * 32 + (2 * t + (sub >> 1)) * 8 + r7;
                uint32_t baddr = b + 20480 + prow * 80 + k16 * 32 + (sub & 1) * 16;
                ldsm4(&Bh[4 * t], baddr);
                ldsm4(&Bl[4 * t], baddr + 10240);
            }
#pragma unroll
            for (int mt = 0; mt < 4; mt++) {
                uint32_t Ah[4], Al[4];
                uint32_t mrow = wco * 64 + mt * 16 + (lane & 15);
                uint32_t aaddr = b + mrow * 80 + k16 * 32 + (lane >> 4) * 16;
                ldsm4(Ah, aaddr);
                ldsm4(Al, aaddr + 10240);
#pragma unroll
                for (int nt = 0; nt < 4; nt++) {
                    float* C = acc + mt * 16 + nt * 4;
                    mma16816(C, Ah, &Bh[2 * nt]);
                    mma16816(C, Ah, &Bl[2 * nt]);
                    mma16816(C, Al, &Bh[2 * nt]);
                }
            }
        }
        __syncthreads();
    }

    // ---- epilogue: stage [px][co] in smem ----
    float* sT = (float*)smem;
#pragma unroll
    for (int mt = 0; mt < 4; mt++)
#pragma unroll
        for (int nt = 0; nt < 4; nt++)
#pragma unroll
            for (int r = 0; r < 4; r++) {
                int row = wco * 64 + mt * 16 + (lane >> 2) + ((r >> 1) << 3);
                int col = wpx * 32 + nt * 8 + ((lane & 3) << 1) + (r & 1);
                sT[col * 132 + row] = acc[mt * 16 + nt * 4 + r];
            }
    __syncthreads();

    int px = tid >> 1, half = tid & 1;
    long srow = (long)n * SS + pxb + px;
    float* sRow = sT + px * 132 + half * 64;
    if (mode != 4) {
        float* dst = outF + srow * cout + co0 + half * 64;
#pragma unroll
        for (int j = 0; j < 64; j += 4) {
            float4 v = *(const float4*)&sRow[j];
            if (mode == 1) {
                float4 cv = *(const float4*)&cvec[n * CC + co0 + half * 64 + j];
                v.x *= cv.x; v.y *= cv.y; v.z *= cv.z; v.w *= cv.w;
            } else if (mode == 2) {
                float4 r4 = *(const float4*)&res[srow * CC + co0 + half * 64 + j];
                v.x = CA * r4.x + CB * v.x; v.y = CA * r4.y + CB * v.y;
                v.z = CA * r4.z + CB * v.z; v.w = CA * r4.w + CB * v.w;
            }
            *(float4*)&dst[j] = v;
        }
    } else {
        const float* rp = res + srow * CC + co0 + half * 64;
#pragma unroll
        for (int j = 0; j < 64; j += 4) {
            float4 r4 = *(const float4*)&rp[j];
            float4 v = *(const float4*)&sRow[j];
            v.x = fminf(fmaxf(CA * r4.x + CB * v.x, -256.f), 256.f);
            v.y = fminf(fmaxf(CA * r4.y + CB * v.y, -256.f), 256.f);
            v.z = fminf(fmaxf(CA * r4.z + CB * v.z, -256.f), 256.f);
            v.w = fminf(fmaxf(CA * r4.w + CB * v.w, -256.f), 256.f);
            *(float4*)&sRow[j] = v;
        }
        __syncthreads();
        int co = tid >> 1, hp = tid & 1;
        float* op = outF + ((long)n * CC + co0 + co) * SS + pxb + hp * 64;
#pragma unroll
        for (int j = 0; j < 64; j += 4) {
            float4 v;
            v.x = sT[(hp * 64 + j + 0) * 132 + co];
            v.y = sT[(hp * 64 + j + 1) * 132 + co];
            v.z = sT[(hp * 64 + j + 2) * 132 + co];
            v.w = sT[(hp * 64 + j + 3) * 132 + co];
            *(float4*)&op[j] = v;
        }
    }
}

// ---------------- qkv normalize + transpose to (N,H,C,S) ----------------
__global__ __launch_bounds__(384) void k_qkvnorm() {
    int s = blockIdx.x, n = blockIdx.y;
    int wid = threadIdx.x >> 5, lane = threadIdx.x & 31;
    int h = wid / 3, which = wid - h * 3;
    long qb = ((long)n * SS + s) * (3 * CC) + h * 192 + which;
    float v0 = g_qkvf[qb + lane * 3];
    float v1 = g_qkvf[qb + (lane + 32) * 3];
    float sum = v0 * v0 + v1 * v1;
#pragma unroll
    for (int o = 16; o > 0; o >>= 1) sum += __shfl_xor_sync(0xffffffffu, sum, o);
    float scale = 1.f / (EPSV + sqrtf(sum) * 0.125f);
    float* dst = (which == 0) ? g_q : (which == 1) ? g_k : g_v;
    long base = ((long)(n * NHEAD + h) * CPH) * SS + s;
    dst[base + (long)lane * SS] = v0 * scale;
    dst[base + (long)(lane + 32) * SS] = v1 * scale;
}

// ---------------- attention: flash-style thread-per-query, fp32 -------------
__global__ __launch_bounds__(128) void k_attn() {
    int nh = blockIdx.y;
    int s = blockIdx.x * 128 + threadIdx.x;
    long off = (long)nh * CPH * SS;
    const float* qp = g_q + off;
    const float* kp = g_k + off;
    const float* vp = g_v + off;
    float q[64];
#pragma unroll
    for (int c = 0; c < 64; c++) q[c] = qp[(long)c * SS + s];
    float m = -1e30f, l = 0.f;
    float acc[64] = {};
    __shared__ __align__(16) float sK[16][68];
    __shared__ __align__(16) float sV[16][68];
    for (int k0 = 0; k0 < SS; k0 += 16) {
        for (int t = threadIdx.x; t < 1024; t += 128) {
            int c = t >> 4, j = t & 15;
            sK[j][c] = kp[(long)c * SS + k0 + j];
            sV[j][c] = vp[(long)c * SS + k0 + j];
        }
        __syncthreads();
        float sc[16];
        float tmax = -1e30f;
#pragma unroll
        for (int j = 0; j < 16; j++) {
            float d = 0.f;
#pragma unroll
            for (int c = 0; c < 64; c += 4) {
                float4 k4 = *(const float4*)&sK[j][c];
                d += q[c] * k4.x + q[c + 1] * k4.y + q[c + 2] * k4.z + q[c + 3] * k4.w;
            }
            d *= 0.125f;
            sc[j] = d;
            tmax = fmaxf(tmax, d);
        }
        float mn = fmaxf(m, tmax);
        float corr = __expf(m - mn);
        l *= corr;
#pragma unroll
        for (int c = 0; c < 64; c++) acc[c] *= corr;
#pragma unroll
        for (int j = 0; j < 16; j++) {
            float p = __expf(sc[j] - mn);
            l += p;
#pragma unroll
            for (int c = 0; c < 64; c += 4) {
                float4 v4 = *(const float4*)&sV[j][c];
                acc[c] += p * v4.x; acc[c + 1] += p * v4.y;
                acc[c + 2] += p * v4.z; acc[c + 3] += p * v4.w;
            }
        }
        m = mn;
        __syncthreads();
    }
    float inv = 1.f / l;
    // write split channel-last: [(n*SS+s)*256 + h*64 + c]
    int n = nh >> 2, h = nh & 3;
    long ob = ((long)n * SS + s) * CC + h * 64;
    uint32_t hw[32], lw[32];
#pragma unroll
    for (int c = 0; c < 64; c += 2) {
        bf16 h0, l0, h1, l1;
        split2(acc[c] * inv, h0, l0);
        split2(acc[c + 1] * inv, h1, l1);
        hw[c >> 1] = pack2(h0, h1);
        lw[c >> 1] = pack2(l0, l1);
    }
#pragma unroll
    for (int c = 0; c < 8; c++) {
        *(uint4*)(g_hB + ob + c * 8) = *(uint4*)&hw[c * 4];
        *(uint4*)(g_lB + ob + c * 8) = *(uint4*)&lw[c * 4];
    }
}

// ---------------- launcher ----------------
extern "C" void kernel_launch(void* const* d_in, const int* in_sizes, int n_in,
                              void* d_out, int out_size) {
    const float* x      = (const float*)d_in[0];
    const float* emb    = (const float*)d_in[1];
    const float* w_skip = (const float*)d_in[2];
    const float* w_res0 = (const float*)d_in[3];
    const float* w_res1 = (const float*)d_in[4];
    const float* w_emb  = (const float*)d_in[5];
    const float* emb_g  = (const float*)d_in[6];
    const float* w_qkv  = (const float*)d_in[7];
    const float* w_proj = (const float*)d_in[8];
    float* out = (float*)d_out;

    bf16 *p_hA, *p_lA, *p_hB, *p_lB;
    bf16 *wh_skip, *wl_skip, *wh_res0, *wl_res0, *wh_res1, *wl_res1;
    bf16 *wh_qkv, *wl_qkv, *wh_proj, *wl_proj;
    float *p_wemb, *p_x, *p_y, *p_qkvf, *p_c;
    cudaGetSymbolAddress((void**)&p_hA, g_hA);
    cudaGetSymbolAddress((void**)&p_lA, g_lA);
    cudaGetSymbolAddress((void**)&p_hB, g_hB);
    cudaGetSymbolAddress((void**)&p_lB, g_lB);
    cudaGetSymbolAddress((void**)&wh_skip, g_wh_skip);
    cudaGetSymbolAddress((void**)&wl_skip, g_wl_skip);
    cudaGetSymbolAddress((void**)&wh_res0, g_wh_res0);
    cudaGetSymbolAddress((void**)&wl_res0, g_wl_res0);
    cudaGetSymbolAddress((void**)&wh_res1, g_wh_res1);
    cudaGetSymbolAddress((void**)&wl_res1, g_wl_res1);
    cudaGetSymbolAddress((void**)&wh_qkv, g_wh_qkv);
    cudaGetSymbolAddress((void**)&wl_qkv, g_wl_qkv);
    cudaGetSymbolAddress((void**)&wh_proj, g_wh_proj);
    cudaGetSymbolAddress((void**)&wl_proj, g_wl_proj);
    cudaGetSymbolAddress((void**)&p_wemb, g_wemb);
    cudaGetSymbolAddress((void**)&p_x, g_x);
    cudaGetSymbolAddress((void**)&p_y, g_y);
    cudaGetSymbolAddress((void**)&p_qkvf, g_qkvf);
    cudaGetSymbolAddress((void**)&p_c, g_c);

    cudaFuncSetAttribute(k_gemm, cudaFuncAttributeMaxDynamicSharedMemorySize, GSMEM);

    // weight prep
    k_wprep<<<CC, 256>>>(w_skip, wh_skip, wl_skip, CIN, 1);
    k_wprep<<<CC, 256>>>(w_res0, wh_res0, wl_res0, CC, 9);
    k_wprep<<<CC, 256>>>(w_res1, wh_res1, wl_res1, CC, 9);
    k_wprep<<<3 * CC, 256>>>(w_qkv, wh_qkv, wl_qkv, CC, 1);
    k_wprep<<<CC, 256>>>(w_proj, wh_proj, wl_proj, CC, 1);
    k_wnorm<<<CC, 256>>>(w_emb, p_wemb, CE, emb_g);
    k_emb<<<NB, 256>>>(emb);

    // input NCHW -> channel-last hi/lo
    k_split0<<<dim3(SS / 32, CIN / 32, NB), 256>>>(x);

    // skip conv (192->256), fp32 channel-last
    k_gemm<<<dim3(8, 2, NB), 256, GSMEM>>>(p_hA, p_lA, wh_skip, wl_skip,
                                           p_x, nullptr, nullptr, CIN, CC, 1, 0);
    // pixel norm + silu split -> hA/lA
    k_pixnorm<<<NB * SS / 8, 256>>>(p_x);

    // res0: y = conv3x3(silu(x)) * c
    k_gemm<<<dim3(8, 2, NB), 256, GSMEM>>>(p_hA, p_lA, wh_res0, wl_res0,
                                           p_y, nullptr, p_c, CC, CC, 9, 1);
    // silu split of y -> hB/lB
    k_split<<<NB * SS * CC / 1024, 256>>>(p_y, p_hB, p_lB, 1);
    // res1: x = CA*x + CB*conv3x3(silu(y))   (in place on x)
    k_gemm<<<dim3(8, 2, NB), 256, GSMEM>>>(p_hB, p_lB, wh_res1, wl_res1,
                                           p_x, p_x, nullptr, CC, CC, 9, 2);
    // split x -> hA/lA (no silu) for qkv conv
    k_split<<<NB * SS * CC / 1024, 256>>>(p_x, p_hA, p_lA, 0);
    // qkv conv (256->768)
    k_gemm<<<dim3(8, 6, NB), 256, GSMEM>>>(p_hA, p_lA, wh_qkv, wl_qkv,
                                           p_qkvf, nullptr, nullptr, CC, 3 * CC, 1, 0);
    // normalize + transpose
    k_qkvnorm<<<dim3(SS, NB), 384>>>();
    // attention (writes split hB/lB channel-last)
    k_attn<<<dim3(8, NB * NHEAD), 128>>>();
    // proj + mp_sum + clip -> d_out (NCHW)
    k_gemm<<<dim3(8, 2, NB), 256, GSMEM>>>(p_hB, p_lB, wh_proj, wl_proj,
                                           out, p_x, nullptr, CC, CC, 1, 4);
}

// round 4
// speedup vs baseline: 2.4463x; 1.1191x over previous
#include <cuda_runtime.h>
#include <cuda_bf16.h>
#include <math.h>
#include <stdint.h>

#define NB   16
#define CC   256
#define CIN  192
#define CE   768
#define HH   32
#define WW   32
#define SS   1024
#define NHEAD 4
#define CPH  64

#define EPSV 1e-4f
#define SILU_SCALE 1.6778523489932886f   // 1/0.596
#define CA 0.9191450300180579f           // 0.7/sqrt(0.58)
#define CB 0.3939192985791677f           // 0.3/sqrt(0.58)

typedef __nv_bfloat16 bf16;

// ---------------- static device scratch ----------------
__device__ bf16 g_hA[NB * SS * CC];
__device__ bf16 g_lA[NB * SS * CC];
__device__ bf16 g_hB[NB * SS * CC];
__device__ bf16 g_lB[NB * SS * CC];
__device__ bf16 g_wh_skip[CC * CIN],    g_wl_skip[CC * CIN];
__device__ bf16 g_wh_res0[CC * CC * 9], g_wl_res0[CC * CC * 9];
__device__ bf16 g_wh_res1[CC * CC * 9], g_wl_res1[CC * CC * 9];
__device__ bf16 g_wh_qkv[3 * CC * CC],  g_wl_qkv[3 * CC * CC];
__device__ bf16 g_wh_proj[CC * CC],     g_wl_proj[CC * CC];
__device__ float g_wemb[CC * CE];
__device__ float g_c[NB * CC];
__device__ float g_x[NB * SS * CC];         // channel-last fp32
__device__ float g_qkvf[NB * SS * 3 * CC];  // channel-last fp32
// attention operands, [nh][s][64] bf16 hi/lo
__device__ bf16 g_qh[64 * SS * 64], g_ql[64 * SS * 64];
__device__ bf16 g_kh[64 * SS * 64], g_kl[64 * SS * 64];
__device__ bf16 g_vh[64 * SS * 64], g_vl[64 * SS * 64];

__device__ __forceinline__ float mp_silu(float v) {
    return v / (1.f + __expf(-v)) * SILU_SCALE;
}
__device__ __forceinline__ void split2(float v, bf16& h, bf16& l) {
    h = __float2bfloat16(v);
    l = __float2bfloat16(v - __bfloat162float(h));
}
__device__ __forceinline__ uint32_t pack2(bf16 a, bf16 b) {
    return (uint32_t)__bfloat16_as_ushort(a) | ((uint32_t)__bfloat16_as_ushort(b) << 16);
}
__device__ __forceinline__ uint32_t packf(float a, float b) {
    return pack2(__float2bfloat16(a), __float2bfloat16(b));
}
__device__ __forceinline__ uint32_t smem_u32(const void* p) {
    uint32_t a;
    asm("{ .reg .u64 t; cvta.to.shared.u64 t, %1; cvt.u32.u64 %0, t; }" : "=r"(a) : "l"(p));
    return a;
}
__device__ __forceinline__ void cpa16(uint32_t d, const void* s, int sz) {
    asm volatile("cp.async.cg.shared.global [%0], [%1], 16, %2;"
                 :: "r"(d), "l"(s), "r"(sz));
}
__device__ __forceinline__ void ldsm4(uint32_t* r, uint32_t addr) {
    asm volatile("ldmatrix.sync.aligned.m8n8.x4.shared.b16 {%0,%1,%2,%3}, [%4];"
                 : "=r"(r[0]), "=r"(r[1]), "=r"(r[2]), "=r"(r[3]) : "r"(addr));
}
__device__ __forceinline__ void ldsm4t(uint32_t* r, uint32_t addr) {
    asm volatile("ldmatrix.sync.aligned.m8n8.x4.trans.shared.b16 {%0,%1,%2,%3}, [%4];"
                 : "=r"(r[0]), "=r"(r[1]), "=r"(r[2]), "=r"(r[3]) : "r"(addr));
}
__device__ __forceinline__ void mma16816(float* c, const uint32_t* a, const uint32_t* b) {
    asm volatile(
        "mma.sync.aligned.m16n8k16.row.col.f32.bf16.bf16.f32 "
        "{%0,%1,%2,%3}, {%4,%5,%6,%7}, {%8,%9}, {%0,%1,%2,%3};"
        : "+f"(c[0]), "+f"(c[1]), "+f"(c[2]), "+f"(c[3])
        : "r"(a[0]), "r"(a[1]), "r"(a[2]), "r"(a[3]), "r"(b[0]), "r"(b[1]));
}

// ---------------- weight prep ----------------
__global__ void k_wprep(const float* __restrict__ w, bf16* __restrict__ oh,
                        bf16* __restrict__ ol, int cin, int taps) {
    int o = blockIdx.x;
    int fan = cin * taps;
    const float* row = w + (long)o * fan;
    float s = 0.f;
    for (int i = threadIdx.x; i < fan; i += 256) { float v = row[i]; s += v * v; }
    __shared__ float red[256];
    red[threadIdx.x] = s;
    __syncthreads();
    for (int off = 128; off > 0; off >>= 1) {
        if (threadIdx.x < off) red[threadIdx.x] += red[threadIdx.x + off];
        __syncthreads();
    }
    float sf = sqrtf((float)fan);
    float scale = 1.f / (sf * (EPSV + sqrtf(red[0]) / sf));
    for (int i = threadIdx.x; i < fan; i += 256) {
        int ci = i / taps, tap = i - ci * taps;
        bf16 h, l;
        split2(row[i] * scale, h, l);
        long oi = (long)o * fan + tap * cin + ci;
        oh[oi] = h;
        ol[oi] = l;
    }
}

__global__ void k_wnorm(const float* __restrict__ w, float* __restrict__ out,
                        int fanin, const float* __restrict__ gain_ptr) {
    int o = blockIdx.x;
    const float* row = w + (long)o * fanin;
    float s = 0.f;
    for (int i = threadIdx.x; i < fanin; i += 256) { float v = row[i]; s += v * v; }
    __shared__ float red[256];
    red[threadIdx.x] = s;
    __syncthreads();
    for (int off = 128; off > 0; off >>= 1) {
        if (threadIdx.x < off) red[threadIdx.x] += red[threadIdx.x + off];
        __syncthreads();
    }
    float g = gain_ptr ? *gain_ptr : 1.0f;
    float sf = sqrtf((float)fanin);
    float scale = g / (sf * (EPSV + sqrtf(red[0]) / sf));
    for (int i = threadIdx.x; i < fanin; i += 256)
        out[(long)o * fanin + i] = row[i] * scale;
}

__global__ void k_emb(const float* __restrict__ emb) {
    int n = blockIdx.x, co = threadIdx.x;
    const float* e = emb + n * CE;
    const float* wr = g_wemb + (long)co * CE;
    float a = 0.f;
    for (int k = 0; k < CE; k++) a += e[k] * wr[k];
    g_c[n * CC + co] = a + 1.0f;
}

// ---------------- input NCHW (192ch) -> channel-last hi/lo ----------------
__global__ __launch_bounds__(256) void k_split0(const float* __restrict__ in) {
    __shared__ float t[32][33];
    int s0 = blockIdx.x * 32, c0 = blockIdx.y * 32, n = blockIdx.z;
    int li = threadIdx.x & 31, gi = threadIdx.x >> 5;
#pragma unroll
    for (int it = 0; it < 4; it++) {
        int c = gi + it * 8;
        t[c][li] = in[((long)n * CIN + c0 + c) * SS + s0 + li];
    }
    __syncthreads();
#pragma unroll
    for (int it = 0; it < 4; it++) {
        int s = gi + it * 8;
        float v = t[li][s];
        bf16 h, l;
        split2(v, h, l);
        long oi = ((long)n * SS + s0 + s) * CIN + c0 + li;
        g_hA[oi] = h;
        g_lA[oi] = l;
    }
}

// ---------------- pixel norm + silu split ----------------
__global__ __launch_bounds__(256) void k_pixnorm(float* __restrict__ x) {
    int row = blockIdx.x * 8 + (threadIdx.x >> 5);
    int lane = threadIdx.x & 31;
    long base = (long)row * CC + lane * 8;
    float4 a = *(const float4*)(x + base);
    float4 b = *(const float4*)(x + base + 4);
    float s = a.x * a.x + a.y * a.y + a.z * a.z + a.w * a.w
            + b.x * b.x + b.y * b.y + b.z * b.z + b.w * b.w;
#pragma unroll
    for (int o = 16; o > 0; o >>= 1) s += __shfl_xor_sync(0xffffffffu, s, o);
    float scale = 1.f / (EPSV + sqrtf(s) * 0.0625f);
    float v[8] = {a.x, a.y, a.z, a.w, b.x, b.y, b.z, b.w};
    bf16 h[8], l[8];
#pragma unroll
    for (int i = 0; i < 8; i++) {
        v[i] *= scale;
        split2(mp_silu(v[i]), h[i], l[i]);
    }
    *(float4*)(x + base) = make_float4(v[0], v[1], v[2], v[3]);
    *(float4*)(x + base + 4) = make_float4(v[4], v[5], v[6], v[7]);
    uint4 ph = make_uint4(pack2(h[0], h[1]), pack2(h[2], h[3]), pack2(h[4], h[5]), pack2(h[6], h[7]));
    uint4 pl = make_uint4(pack2(l[0], l[1]), pack2(l[2], l[3]), pack2(l[4], l[5]), pack2(l[6], l[7]));
    *(uint4*)(g_hA + base) = ph;
    *(uint4*)(g_lA + base) = pl;
}

// ---------------- mma.sync GEMM / implicit conv ----------------
// modes: 0 plain fp32; 1 *c + silu -> split only; 2 mp_sum -> fp32 + split;
//        4 mp_sum + clip -> NCHW fp32
#define GSMEM 81920
__global__ __launch_bounds__(256) void k_gemm(
    const bf16* __restrict__ inH, const bf16* __restrict__ inL,
    const bf16* __restrict__ wH, const bf16* __restrict__ wL,
    float* __restrict__ outF, bf16* __restrict__ outH, bf16* __restrict__ outL,
    const float* __restrict__ res, const float* __restrict__ cvec,
    int cin, int cout, int taps, int mode) {
    extern __shared__ char smem[];
    const int tid = threadIdx.x, lane = tid & 31, wid = tid >> 5;
    const int n = blockIdx.z, co0 = blockIdx.y * 128, pxb = blockIdx.x * 128;
    const int wco = wid >> 2, wpx = wid & 3;
    const int cpt = cin >> 5;
    const int nch = taps * cpt;
    const long Ktot = (long)taps * cin;
    const uint32_t sbase = smem_u32(smem);

    float acc[64];
#pragma unroll
    for (int i = 0; i < 64; i++) acc[i] = 0.f;

    auto load_chunk = [&](int c, int buf) {
        int tap = c / cpt;
        int ci0 = (c - tap * cpt) << 5;
        int dy = (taps == 9) ? tap / 3 - 1 : 0;
        int dx = (taps == 9) ? tap % 3 - 1 : 0;
        uint32_t b = sbase + buf * 40960;
#pragma unroll
        for (int rep = 0; rep < 2; rep++) {
            int idx = tid + rep * 256;
            int r = idx >> 2, seg = idx & 3;
            uint32_t dA = b + r * 80 + seg * 16;
            long aoff = (long)(co0 + r) * Ktot + c * 32 + seg * 8;
            cpa16(dA, wH + aoff, 16);
            cpa16(dA + 10240, wL + aoff, 16);
        }
#pragma unroll
        for (int rep = 0; rep < 2; rep++) {
            int idx = tid + rep * 256;
            int p = idx >> 2, seg = idx & 3;
            int s = pxb + p;
            int hh = (s >> 5) + dy, ww = (s & 31) + dx;
            int valid = ((unsigned)hh < 32u) && ((unsigned)ww < 32u);
            long soff = ((long)n * SS + (valid ? hh * 32 + ww : 0)) * cin + ci0 + seg * 8;
            uint32_t dB = b + 20480 + p * 80 + seg * 16;
            int sz = valid ? 16 : 0;
            cpa16(dB, inH + soff, sz);
            cpa16(dB + 10240, inL + soff, sz);
        }
        asm volatile("cp.async.commit_group;" ::: "memory");
    };

    load_chunk(0, 0);
    for (int c = 0; c < nch; c++) {
        int buf = c & 1;
        if (c + 1 < nch) {
            load_chunk(c + 1, buf ^ 1);
            asm volatile("cp.async.wait_group 1;" ::: "memory");
        } else {
            asm volatile("cp.async.wait_group 0;" ::: "memory");
        }
        __syncthreads();
        uint32_t b = sbase + buf * 40960;
#pragma unroll
        for (int k16 = 0; k16 < 2; k16++) {
            uint32_t Bh[8], Bl[8];
#pragma unroll
            for (int t = 0; t < 2; t++) {
                int sub = lane >> 3, r7 = lane & 7;
                uint32_t prow = wpx * 32 + (2 * t + (sub >> 1)) * 8 + r7;
                uint32_t baddr = b + 20480 + prow * 80 + k16 * 32 + (sub & 1) * 16;
                ldsm4(&Bh[4 * t], baddr);
                ldsm4(&Bl[4 * t], baddr + 10240);
            }
#pragma unroll
            for (int mt = 0; mt < 4; mt++) {
                uint32_t Ah[4], Al[4];
                uint32_t mrow = wco * 64 + mt * 16 + (lane & 15);
                uint32_t aaddr = b + mrow * 80 + k16 * 32 + (lane >> 4) * 16;
                ldsm4(Ah, aaddr);
                ldsm4(Al, aaddr + 10240);
#pragma unroll
                for (int nt = 0; nt < 4; nt++) {
                    float* C = acc + mt * 16 + nt * 4;
                    mma16816(C, Ah, &Bh[2 * nt]);
                    mma16816(C, Ah, &Bl[2 * nt]);
                    mma16816(C, Al, &Bh[2 * nt]);
                }
            }
        }
        __syncthreads();
    }

    // ---- epilogue ----
    float* sT = (float*)smem;
#pragma unroll
    for (int mt = 0; mt < 4; mt++)
#pragma unroll
        for (int nt = 0; nt < 4; nt++)
#pragma unroll
            for (int r = 0; r < 4; r++) {
                int row = wco * 64 + mt * 16 + (lane >> 2) + ((r >> 1) << 3);
                int col = wpx * 32 + nt * 8 + ((lane & 3) << 1) + (r & 1);
                sT[col * 132 + row] = acc[mt * 16 + nt * 4 + r];
            }
    __syncthreads();

    int px = tid >> 1, half = tid & 1;
    long srow = (long)n * SS + pxb + px;
    float* sRow = sT + px * 132 + half * 64;
    if (mode == 0) {
        float* dst = outF + srow * cout + co0 + half * 64;
#pragma unroll
        for (int j = 0; j < 64; j += 4)
            *(float4*)&dst[j] = *(const float4*)&sRow[j];
    } else if (mode == 1) {
        long ob = srow * CC + co0 + half * 64;
#pragma unroll
        for (int j = 0; j < 64; j += 4) {
            float4 v = *(const float4*)&sRow[j];
            float4 cv = *(const float4*)&cvec[n * CC + co0 + half * 64 + j];
            float f0 = mp_silu(v.x * cv.x), f1 = mp_silu(v.y * cv.y);
            float f2 = mp_silu(v.z * cv.z), f3 = mp_silu(v.w * cv.w);
            bf16 h0, l0, h1, l1, h2, l2, h3, l3;
            split2(f0, h0, l0); split2(f1, h1, l1);
            split2(f2, h2, l2); split2(f3, h3, l3);
            *(uint2*)(outH + ob + j) = make_uint2(pack2(h0, h1), pack2(h2, h3));
            *(uint2*)(outL + ob + j) = make_uint2(pack2(l0, l1), pack2(l2, l3));
        }
    } else if (mode == 2) {
        long ob = srow * CC + co0 + half * 64;
        float* dst = outF + ob;
#pragma unroll
        for (int j = 0; j < 64; j += 4) {
            float4 v = *(const float4*)&sRow[j];
            float4 r4 = *(const float4*)&res[ob + j];
            v.x = CA * r4.x + CB * v.x; v.y = CA * r4.y + CB * v.y;
            v.z = CA * r4.z + CB * v.z; v.w = CA * r4.w + CB * v.w;
            *(float4*)&dst[j] = v;
            bf16 h0, l0, h1, l1, h2, l2, h3, l3;
            split2(v.x, h0, l0); split2(v.y, h1, l1);
            split2(v.z, h2, l2); split2(v.w, h3, l3);
            *(uint2*)(outH + ob + j) = make_uint2(pack2(h0, h1), pack2(h2, h3));
            *(uint2*)(outL + ob + j) = make_uint2(pack2(l0, l1), pack2(l2, l3));
        }
    } else {
        const float* rp = res + srow * CC + co0 + half * 64;
#pragma unroll
        for (int j = 0; j < 64; j += 4) {
            float4 r4 = *(const float4*)&rp[j];
            float4 v = *(const float4*)&sRow[j];
            v.x = fminf(fmaxf(CA * r4.x + CB * v.x, -256.f), 256.f);
            v.y = fminf(fmaxf(CA * r4.y + CB * v.y, -256.f), 256.f);
            v.z = fminf(fmaxf(CA * r4.z + CB * v.z, -256.f), 256.f);
            v.w = fminf(fmaxf(CA * r4.w + CB * v.w, -256.f), 256.f);
            *(float4*)&sRow[j] = v;
        }
        __syncthreads();
        int co = tid >> 1, hp = tid & 1;
        float* op = outF + ((long)n * CC + co0 + co) * SS + pxb + hp * 64;
#pragma unroll
        for (int j = 0; j < 64; j += 4) {
            float4 v;
            v.x = sT[(hp * 64 + j + 0) * 132 + co];
            v.y = sT[(hp * 64 + j + 1) * 132 + co];
            v.z = sT[(hp * 64 + j + 2) * 132 + co];
            v.w = sT[(hp * 64 + j + 3) * 132 + co];
            *(float4*)&op[j] = v;
        }
    }
}

// ---------------- qkv normalize -> bf16 hi/lo [nh][s][64] ----------------
__global__ __launch_bounds__(384) void k_qkvnorm() {
    int s = blockIdx.x, n = blockIdx.y;
    int wid = threadIdx.x >> 5, lane = threadIdx.x & 31;
    int h = wid / 3, which = wid - h * 3;
    long qb = ((long)n * SS + s) * (3 * CC) + h * 192 + which;
    float v0 = g_qkvf[qb + lane * 3];
    float v1 = g_qkvf[qb + (lane + 32) * 3];
    float sum = v0 * v0 + v1 * v1;
#pragma unroll
    for (int o = 16; o > 0; o >>= 1) sum += __shfl_xor_sync(0xffffffffu, sum, o);
    float scale = 1.f / (EPSV + sqrtf(sum) * 0.125f);
    v0 *= scale; v1 *= scale;
    bf16* dh = (which == 0) ? g_qh : (which == 1) ? g_kh : g_vh;
    bf16* dl = (which == 0) ? g_ql : (which == 1) ? g_kl : g_vl;
    long base = ((long)(n * NHEAD + h) * SS + s) * 64;
    bf16 h0, l0, h1, l1;
    split2(v0, h0, l0);
    split2(v1, h1, l1);
    dh[base + lane] = h0; dh[base + lane + 32] = h1;
    dl[base + lane] = l0; dl[base + lane + 32] = l1;
}

// ---------------- MMA flash attention ----------------
// block: 128 queries (8 warps x 16 rows), KV tiles of 64, double-buffered
#define ATT_SMEM (2 * 36864)
__global__ __launch_bounds__(256, 1) void k_fattn() {
    extern __shared__ char smem[];
    const int tid = threadIdx.x, lane = tid & 31, wid = tid >> 5;
    const int nh = blockIdx.y, qb = blockIdx.x * 128;
    const int n = nh >> 2, h = nh & 3;
    const uint32_t sb = smem_u32(smem);
    const long nhb = (long)nh * SS * 64;
    const bf16* kh = g_kh + nhb;
    const bf16* kl = g_kl + nhb;
    const bf16* vh = g_vh + nhb;
    const bf16* vl = g_vl + nhb;

    // ---- stage Q, build fragments ----
    {
        const bf16* qh = g_qh + nhb + (long)qb * 64;
        const bf16* ql = g_ql + nhb + (long)qb * 64;
        for (int i = tid; i < 1024; i += 256) {
            int r = i >> 3, seg = i & 7;
            uint32_t d = sb + r * 144 + seg * 16;
            cpa16(d, qh + r * 64 + seg * 8, 16);
            cpa16(d + 18432, ql + r * 64 + seg * 8, 16);
        }
        asm volatile("cp.async.commit_group;" ::: "memory");
        asm volatile("cp.async.wait_group 0;" ::: "memory");
        __syncthreads();
    }
    uint32_t qhf[4][4], qlf[4][4];
    {
        int r = wid * 16 + (lane & 15);
        int halfk = lane >> 4;
#pragma unroll
        for (int kc = 0; kc < 4; kc++) {
            uint32_t addr = sb + r * 144 + (kc * 16 + halfk * 8) * 2;
            ldsm4(qhf[kc], addr);
            ldsm4(qlf[kc], addr + 18432);
        }
    }
    __syncthreads();

    auto load_kv = [&](int t, int buf) {
        uint32_t b = sb + buf * 36864;
#pragma unroll
        for (int rep = 0; rep < 2; rep++) {
            int i = tid + rep * 256;
            int r = i >> 3, seg = i & 7;
            long off = ((long)t * 64 + r) * 64 + seg * 8;
            uint32_t d = b + r * 144 + seg * 16;
            cpa16(d, kh + off, 16);
            cpa16(d + 9216, kl + off, 16);
            cpa16(d + 18432, vh + off, 16);
            cpa16(d + 27648, vl + off, 16);
        }
        asm volatile("cp.async.commit_group;" ::: "memory");
    };

    float m0 = -1e30f, m1 = -1e30f, l0 = 0.f, l1 = 0.f;
    float acc[8][4];
#pragma unroll
    for (int j = 0; j < 8; j++)
#pragma unroll
        for (int i = 0; i < 4; i++) acc[j][i] = 0.f;

    load_kv(0, 0);
    for (int t = 0; t < 16; t++) {
        int buf = t & 1;
        if (t + 1 < 16) {
            load_kv(t + 1, buf ^ 1);
            asm volatile("cp.async.wait_group 1;" ::: "memory");
        } else {
            asm volatile("cp.async.wait_group 0;" ::: "memory");
        }
        __syncthreads();
        uint32_t kb = sb + buf * 36864;

        // ---- scores S = Q K^T ----
        float sc[8][4];
#pragma unroll
        for (int j = 0; j < 8; j++)
#pragma unroll
            for (int i = 0; i < 4; i++) sc[j][i] = 0.f;
        const int g = lane >> 3, r7 = lane & 7;
#pragma unroll
        for (int ntp = 0; ntp < 4; ntp++) {
#pragma unroll
            for (int kc = 0; kc < 4; kc++) {
                uint32_t bh[4], bl[4];
                uint32_t ka = kb + (ntp * 16 + (g >> 1) * 8 + r7) * 144
                            + (kc * 16 + (g & 1) * 8) * 2;
                ldsm4(bh, ka);
                ldsm4(bl, ka + 9216);
                mma16816(sc[2 * ntp], qhf[kc], bh);
                mma16816(sc[2 * ntp], qhf[kc], bl);
                mma16816(sc[2 * ntp], qlf[kc], bh);
                mma16816(sc[2 * ntp + 1], qhf[kc], bh + 2);
                mma16816(sc[2 * ntp + 1], qhf[kc], bl + 2);
                mma16816(sc[2 * ntp + 1], qlf[kc], bh + 2);
            }
        }
        // ---- softmax ----
        float mx0 = -1e30f, mx1 = -1e30f;
#pragma unroll
        for (int j = 0; j < 8; j++) {
#pragma unroll
            for (int i = 0; i < 4; i++) sc[j][i] *= 0.125f;
            mx0 = fmaxf(mx0, fmaxf(sc[j][0], sc[j][1]));
            mx1 = fmaxf(mx1, fmaxf(sc[j][2], sc[j][3]));
        }
        mx0 = fmaxf(mx0, __shfl_xor_sync(0xffffffffu, mx0, 1));
        mx0 = fmaxf(mx0, __shfl_xor_sync(0xffffffffu, mx0, 2));
        mx1 = fmaxf(mx1, __shfl_xor_sync(0xffffffffu, mx1, 1));
        mx1 = fmaxf(mx1, __shfl_xor_sync(0xffffffffu, mx1, 2));
        float nm0 = fmaxf(m0, mx0), nm1 = fmaxf(m1, mx1);
        float f0 = __expf(m0 - nm0), f1 = __expf(m1 - nm1);
        m0 = nm0; m1 = nm1;
        l0 *= f0; l1 *= f1;
#pragma unroll
        for (int j = 0; j < 8; j++) {
            sc[j][0] = __expf(sc[j][0] - nm0);
            sc[j][1] = __expf(sc[j][1] - nm0);
            sc[j][2] = __expf(sc[j][2] - nm1);
            sc[j][3] = __expf(sc[j][3] - nm1);
            l0 += sc[j][0] + sc[j][1];
            l1 += sc[j][2] + sc[j][3];
        }
#pragma unroll
        for (int j = 0; j < 8; j++) {
            acc[j][0] *= f0; acc[j][1] *= f0;
            acc[j][2] *= f1; acc[j][3] *= f1;
        }
        // ---- O += P V ----
#pragma unroll
        for (int kk = 0; kk < 4; kk++) {
            uint32_t ph[4], pl[4];
#pragma unroll
            for (int half = 0; half < 2; half++) {
                int j = 2 * kk + half;
                bf16 h00, l00, h01, l01, h10, l10, h11, l11;
                split2(sc[j][0], h00, l00);
                split2(sc[j][1], h01, l01);
                split2(sc[j][2], h10, l10);
                split2(sc[j][3], h11, l11);
                ph[2 * half] = pack2(h00, h01);
                ph[2 * half + 1] = pack2(h10, h11);
                pl[2 * half] = pack2(l00, l01);
                pl[2 * half + 1] = pack2(l10, l11);
            }
#pragma unroll
            for (int ctp = 0; ctp < 4; ctp++) {
                uint32_t vh4[4], vl4[4];
                uint32_t va = kb + 18432 + (kk * 16 + (g & 1) * 8 + r7) * 144
                            + (ctp * 16 + (g >> 1) * 8) * 2;
                ldsm4t(vh4, va);
                ldsm4t(vl4, va + 9216);
                mma16816(acc[2 * ctp], ph, vh4);
                mma16816(acc[2 * ctp], ph, vl4);
                mma16816(acc[2 * ctp], pl, vh4);
                mma16816(acc[2 * ctp + 1], ph, vh4 + 2);
                mma16816(acc[2 * ctp + 1], ph, vl4 + 2);
                mma16816(acc[2 * ctp + 1], pl, vh4 + 2);
            }
        }
        __syncthreads();
    }

    // ---- finalize ----
    l0 += __shfl_xor_sync(0xffffffffu, l0, 1);
    l0 += __shfl_xor_sync(0xffffffffu, l0, 2);
    l1 += __shfl_xor_sync(0xffffffffu, l1, 1);
    l1 += __shfl_xor_sync(0xffffffffu, l1, 2);
    float i0 = 1.f / l0, i1 = 1.f / l1;
    int rr = lane >> 2, t4 = lane & 3;
    int s0r = qb + wid * 16 + rr;
    long b0 = ((long)n * SS + s0r) * CC + h * 64;
    long b1 = ((long)n * SS + s0r + 8) * CC + h * 64;
#pragma unroll
    for (int j = 0; j < 8; j++) {
        int ch = j * 8 + t4 * 2;
        float v0 = acc[j][0] * i0, v1 = acc[j][1] * i0;
        float v2 = acc[j][2] * i1, v3 = acc[j][3] * i1;
        bf16 h0, lo0, h1, lo1, h2, lo2, h3, lo3;
        split2(v0, h0, lo0); split2(v1, h1, lo1);
        split2(v2, h2, lo2); split2(v3, h3, lo3);
        *(uint32_t*)(g_hB + b0 + ch) = pack2(h0, h1);
        *(uint32_t*)(g_lB + b0 + ch) = pack2(lo0, lo1);
        *(uint32_t*)(g_hB + b1 + ch) = pack2(h2, h3);
        *(uint32_t*)(g_lB + b1 + ch) = pack2(lo2, lo3);
    }
}

// ---------------- launcher ----------------
extern "C" void kernel_launch(void* const* d_in, const int* in_sizes, int n_in,
                              void* d_out, int out_size) {
    const float* x      = (const float*)d_in[0];
    const float* emb    = (const float*)d_in[1];
    const float* w_skip = (const float*)d_in[2];
    const float* w_res0 = (const float*)d_in[3];
    const float* w_res1 = (const float*)d_in[4];
    const float* w_emb  = (const float*)d_in[5];
    const float* emb_g  = (const float*)d_in[6];
    const float* w_qkv  = (const float*)d_in[7];
    const float* w_proj = (const float*)d_in[8];
    float* out = (float*)d_out;

    bf16 *p_hA, *p_lA, *p_hB, *p_lB;
    bf16 *wh_skip, *wl_skip, *wh_res0, *wl_res0, *wh_res1, *wl_res1;
    bf16 *wh_qkv, *wl_qkv, *wh_proj, *wl_proj;
    float *p_wemb, *p_x, *p_qkvf, *p_c;
    cudaGetSymbolAddress((void**)&p_hA, g_hA);
    cudaGetSymbolAddress((void**)&p_lA, g_lA);
    cudaGetSymbolAddress((void**)&p_hB, g_hB);
    cudaGetSymbolAddress((void**)&p_lB, g_lB);
    cudaGetSymbolAddress((void**)&wh_skip, g_wh_skip);
    cudaGetSymbolAddress((void**)&wl_skip, g_wl_skip);
    cudaGetSymbolAddress((void**)&wh_res0, g_wh_res0);
    cudaGetSymbolAddress((void**)&wl_res0, g_wl_res0);
    cudaGetSymbolAddress((void**)&wh_res1, g_wh_res1);
    cudaGetSymbolAddress((void**)&wl_res1, g_wl_res1);
    cudaGetSymbolAddress((void**)&wh_qkv, g_wh_qkv);
    cudaGetSymbolAddress((void**)&wl_qkv, g_wl_qkv);
    cudaGetSymbolAddress((void**)&wh_proj, g_wh_proj);
    cudaGetSymbolAddress((void**)&wl_proj, g_wl_proj);
    cudaGetSymbolAddress((void**)&p_wemb, g_wemb);
    cudaGetSymbolAddress((void**)&p_x, g_x);
    cudaGetSymbolAddress((void**)&p_qkvf, g_qkvf);
    cudaGetSymbolAddress((void**)&p_c, g_c);

    cudaFuncSetAttribute(k_gemm, cudaFuncAttributeMaxDynamicSharedMemorySize, GSMEM);
    cudaFuncSetAttribute(k_fattn, cudaFuncAttributeMaxDynamicSharedMemorySize, ATT_SMEM);

    // weight prep
    k_wprep<<<CC, 256>>>(w_skip, wh_skip, wl_skip, CIN, 1);
    k_wprep<<<CC, 256>>>(w_res0, wh_res0, wl_res0, CC, 9);
    k_wprep<<<CC, 256>>>(w_res1, wh_res1, wl_res1, CC, 9);
    k_wprep<<<3 * CC, 256>>>(w_qkv, wh_qkv, wl_qkv, CC, 1);
    k_wprep<<<CC, 256>>>(w_proj, wh_proj, wl_proj, CC, 1);
    k_wnorm<<<CC, 256>>>(w_emb, p_wemb, CE, emb_g);
    k_emb<<<NB, 256>>>(emb);

    // input NCHW -> channel-last hi/lo
    k_split0<<<dim3(SS / 32, CIN / 32, NB), 256>>>(x);

    // skip conv (192->256) -> fp32 x
    k_gemm<<<dim3(8, 2, NB), 256, GSMEM>>>(p_hA, p_lA, wh_skip, wl_skip,
                                           p_x, nullptr, nullptr, nullptr, nullptr,
                                           CIN, CC, 1, 0);
    // pixel norm + silu split -> hA/lA
    k_pixnorm<<<NB * SS / 8, 256>>>(p_x);
    // res0: silu(conv3x3 * c) -> hB/lB
    k_gemm<<<dim3(8, 2, NB), 256, GSMEM>>>(p_hA, p_lA, wh_res0, wl_res0,
                                           nullptr, p_hB, p_lB, nullptr, p_c,
                                           CC, CC, 9, 1);
    // res1: x = CA*x + CB*conv3x3 -> fp32 x + hA/lA split
    k_gemm<<<dim3(8, 2, NB), 256, GSMEM>>>(p_hB, p_lB, wh_res1, wl_res1,
                                           p_x, p_hA, p_lA, p_x, nullptr,
                                           CC, CC, 9, 2);
    // qkv conv (256->768) -> fp32 qkvf
    k_gemm<<<dim3(8, 6, NB), 256, GSMEM>>>(p_hA, p_lA, wh_qkv, wl_qkv,
                                           p_qkvf, nullptr, nullptr, nullptr, nullptr,
                                           CC, 3 * CC, 1, 0);
    // normalize -> q/k/v hi/lo
    k_qkvnorm<<<dim3(SS, NB), 384>>>();
    // MMA flash attention -> hB/lB
    k_fattn<<<dim3(SS / 128, NB * NHEAD), 256, ATT_SMEM>>>();
    // proj + mp_sum + clip -> d_out (NCHW)
    k_gemm<<<dim3(8, 2, NB), 256, GSMEM>>>(p_hB, p_lB, wh_proj, wl_proj,
                                           out, nullptr, nullptr, p_x, nullptr,
                                           CC, CC, 1, 4);
}

// round 5
// speedup vs baseline: 7.0894x; 2.8980x over previous
#include <cuda_runtime.h>
#include <cuda_fp16.h>
#include <math.h>
#include <stdint.h>

#define NB   16
#define CC   256
#define CIN  192
#define CE   768
#define SS   1024
#define NHEAD 4

#define EPSV 1e-4f
#define SILU_SCALE 1.6778523489932886f   // 1/0.596
#define CA 0.9191450300180579f           // 0.7/sqrt(0.58)
#define CB 0.3939192985791677f           // 0.3/sqrt(0.58)

typedef __half fp16;

// ---------------- static device scratch ----------------
__device__ fp16 g_a16[NB * SS * CC];        // channel-last fp16 activations
__device__ fp16 g_b16[NB * SS * CC];
__device__ fp16 g_w_skip[CC * CIN];
__device__ fp16 g_w_res0[CC * CC * 9];
__device__ fp16 g_w_res1[CC * CC * 9];
__device__ fp16 g_w_qkv[3 * CC * CC];       // rows permuted (h, which, cph)
__device__ fp16 g_w_proj[CC * CC];
__device__ float g_wemb[CC * CE];
__device__ float g_c[NB * CC];
__device__ float g_x[NB * SS * CC];         // channel-last fp32 residual
// attention operands [nh][s][64]
__device__ fp16 g_q16[64 * SS * 64];
__device__ fp16 g_k16[64 * SS * 64];
__device__ fp16 g_v16[64 * SS * 64];

__device__ __forceinline__ float mp_silu(float v) {
    return v / (1.f + __expf(-v)) * SILU_SCALE;
}
__device__ __forceinline__ uint32_t packf(float a, float b) {
    __half2 h = __floats2half2_rn(a, b);
    return *(uint32_t*)&h;
}
__device__ __forceinline__ uint32_t smem_u32(const void* p) {
    uint32_t a;
    asm("{ .reg .u64 t; cvta.to.shared.u64 t, %1; cvt.u32.u64 %0, t; }" : "=r"(a) : "l"(p));
    return a;
}
__device__ __forceinline__ void cpa16(uint32_t d, const void* s, int sz) {
    asm volatile("cp.async.cg.shared.global [%0], [%1], 16, %2;"
                 :: "r"(d), "l"(s), "r"(sz));
}
__device__ __forceinline__ void ldsm4(uint32_t* r, uint32_t addr) {
    asm volatile("ldmatrix.sync.aligned.m8n8.x4.shared.b16 {%0,%1,%2,%3}, [%4];"
                 : "=r"(r[0]), "=r"(r[1]), "=r"(r[2]), "=r"(r[3]) : "r"(addr));
}
__device__ __forceinline__ void ldsm4t(uint32_t* r, uint32_t addr) {
    asm volatile("ldmatrix.sync.aligned.m8n8.x4.trans.shared.b16 {%0,%1,%2,%3}, [%4];"
                 : "=r"(r[0]), "=r"(r[1]), "=r"(r[2]), "=r"(r[3]) : "r"(addr));
}
__device__ __forceinline__ void mma16816(float* c, const uint32_t* a, const uint32_t* b) {
    asm volatile(
        "mma.sync.aligned.m16n8k16.row.col.f32.f16.f16.f32 "
        "{%0,%1,%2,%3}, {%4,%5,%6,%7}, {%8,%9}, {%0,%1,%2,%3};"
        : "+f"(c[0]), "+f"(c[1]), "+f"(c[2]), "+f"(c[3])
        : "r"(a[0]), "r"(a[1]), "r"(a[2]), "r"(a[3]), "r"(b[0]), "r"(b[1]));
}

// ---------------- weight prep: normalize + fp16 + tap-major (+row perm) -----
__global__ void k_wprep(const float* __restrict__ w, fp16* __restrict__ oh,
                        int cin, int taps, int perm) {
    int o = blockIdx.x;
    int fan = cin * taps;
    const float* row = w + (long)o * fan;
    float s = 0.f;
    for (int i = threadIdx.x; i < fan; i += 256) { float v = row[i]; s += v * v; }
    __shared__ float red[256];
    red[threadIdx.x] = s;
    __syncthreads();
    for (int off = 128; off > 0; off >>= 1) {
        if (threadIdx.x < off) red[threadIdx.x] += red[threadIdx.x + off];
        __syncthreads();
    }
    float sf = sqrtf((float)fan);
    float scale = 1.f / (sf * (EPSV + sqrtf(red[0]) / sf));
    int od = o;
    if (perm) {                     // o = h*192 + cph*3 + which -> h*192 + which*64 + cph
        int h = o / 192, r = o - h * 192;
        od = h * 192 + (r % 3) * 64 + r / 3;
    }
    for (int i = threadIdx.x; i < fan; i += 256) {
        int ci = i / taps, tap = i - ci * taps;
        oh[(long)od * fan + tap * cin + ci] = __float2half(row[i] * scale);
    }
}

__global__ void k_wnorm(const float* __restrict__ w, float* __restrict__ out,
                        int fanin, const float* __restrict__ gain_ptr) {
    int o = blockIdx.x;
    const float* row = w + (long)o * fanin;
    float s = 0.f;
    for (int i = threadIdx.x; i < fanin; i += 256) { float v = row[i]; s += v * v; }
    __shared__ float red[256];
    red[threadIdx.x] = s;
    __syncthreads();
    for (int off = 128; off > 0; off >>= 1) {
        if (threadIdx.x < off) red[threadIdx.x] += red[threadIdx.x + off];
        __syncthreads();
    }
    float g = gain_ptr ? *gain_ptr : 1.0f;
    float sf = sqrtf((float)fanin);
    float scale = g / (sf * (EPSV + sqrtf(red[0]) / sf));
    for (int i = threadIdx.x; i < fanin; i += 256)
        out[(long)o * fanin + i] = row[i] * scale;
}

__global__ void k_emb(const float* __restrict__ emb) {
    int n = blockIdx.x, co = threadIdx.x;
    const float* e = emb + n * CE;
    const float* wr = g_wemb + (long)co * CE;
    float a = 0.f;
    for (int k = 0; k < CE; k++) a += e[k] * wr[k];
    g_c[n * CC + co] = a + 1.0f;
}

// ---------------- input NCHW (192ch) -> channel-last fp16 ----------------
__global__ __launch_bounds__(256) void k_split0(const float* __restrict__ in) {
    __shared__ float t[32][33];
    int s0 = blockIdx.x * 32, c0 = blockIdx.y * 32, n = blockIdx.z;
    int li = threadIdx.x & 31, gi = threadIdx.x >> 5;
#pragma unroll
    for (int it = 0; it < 4; it++) {
        int c = gi + it * 8;
        t[c][li] = in[((long)n * CIN + c0 + c) * SS + s0 + li];
    }
    __syncthreads();
#pragma unroll
    for (int it = 0; it < 4; it++) {
        int s = gi + it * 8;
        g_a16[((long)n * SS + s0 + s) * CIN + c0 + li] = __float2half(t[li][s]);
    }
}

// ---------------- pixel norm (fp32, in place) + silu fp16 out ----------------
__global__ __launch_bounds__(256) void k_pixnorm(float* __restrict__ x) {
    int row = blockIdx.x * 8 + (threadIdx.x >> 5);
    int lane = threadIdx.x & 31;
    long base = (long)row * CC + lane * 8;
    float4 a = *(const float4*)(x + base);
    float4 b = *(const float4*)(x + base + 4);
    float s = a.x * a.x + a.y * a.y + a.z * a.z + a.w * a.w
            + b.x * b.x + b.y * b.y + b.z * b.z + b.w * b.w;
#pragma unroll
    for (int o = 16; o > 0; o >>= 1) s += __shfl_xor_sync(0xffffffffu, s, o);
    float scale = 1.f / (EPSV + sqrtf(s) * 0.0625f);
    float v[8] = {a.x, a.y, a.z, a.w, b.x, b.y, b.z, b.w};
    uint32_t pk[4];
#pragma unroll
    for (int i = 0; i < 8; i += 2) {
        v[i] *= scale;
        v[i + 1] *= scale;
        pk[i >> 1] = packf(mp_silu(v[i]), mp_silu(v[i + 1]));
    }
    *(float4*)(x + base) = make_float4(v[0], v[1], v[2], v[3]);
    *(float4*)(x + base + 4) = make_float4(v[4], v[5], v[6], v[7]);
    *(uint4*)(g_a16 + base) = make_uint4(pk[0], pk[1], pk[2], pk[3]);
}

// ---------------- fp16 mma.sync GEMM / implicit conv ----------------
// modes: 0 plain fp32 channel-last; 1 *c + silu -> fp16; 2 mp_sum -> fp32+fp16;
//        3 qkv fused 64ch norm -> q/k/v fp16; 4 mp_sum + clip -> NCHW fp32
#define GSMEM 40960
__global__ __launch_bounds__(256, 2) void k_gemm(
    const fp16* __restrict__ inA, const fp16* __restrict__ wA,
    float* __restrict__ outF, fp16* __restrict__ out16,
    const float* __restrict__ res, const float* __restrict__ cvec,
    int cin, int cout, int taps, int mode) {
    extern __shared__ char smem[];
    const int tid = threadIdx.x, lane = tid & 31, wid = tid >> 5;
    const int n = blockIdx.z, co0 = blockIdx.y * 128, pxb = blockIdx.x * 128;
    const int wco = wid >> 2, wpx = wid & 3;
    const int cpt = cin >> 5;
    const int nch = taps * cpt;
    const long Ktot = (long)taps * cin;
    const uint32_t sbase = smem_u32(smem);

    float acc[64];
#pragma unroll
    for (int i = 0; i < 64; i++) acc[i] = 0.f;

    auto load_chunk = [&](int c, int buf) {
        int tap = c / cpt;
        int ci0 = (c - tap * cpt) << 5;
        int dy = (taps == 9) ? tap / 3 - 1 : 0;
        int dx = (taps == 9) ? tap % 3 - 1 : 0;
        uint32_t b = sbase + buf * 20480;
#pragma unroll
        for (int rep = 0; rep < 2; rep++) {
            int idx = tid + rep * 256;
            int r = idx >> 2, seg = idx & 3;
            long aoff = (long)(co0 + r) * Ktot + c * 32 + seg * 8;
            cpa16(b + r * 80 + seg * 16, wA + aoff, 16);
        }
#pragma unroll
        for (int rep = 0; rep < 2; rep++) {
            int idx = tid + rep * 256;
            int p = idx >> 2, seg = idx & 3;
            int s = pxb + p;
            int hh = (s >> 5) + dy, ww = (s & 31) + dx;
            int valid = ((unsigned)hh < 32u) && ((unsigned)ww < 32u);
            long soff = ((long)n * SS + (valid ? hh * 32 + ww : 0)) * cin + ci0 + seg * 8;
            cpa16(b + 10240 + p * 80 + seg * 16, inA + soff, valid ? 16 : 0);
        }
        asm volatile("cp.async.commit_group;" ::: "memory");
    };

    load_chunk(0, 0);
    for (int c = 0; c < nch; c++) {
        int buf = c & 1;
        if (c + 1 < nch) {
            load_chunk(c + 1, buf ^ 1);
            asm volatile("cp.async.wait_group 1;" ::: "memory");
        } else {
            asm volatile("cp.async.wait_group 0;" ::: "memory");
        }
        __syncthreads();
        uint32_t b = sbase + buf * 20480;
#pragma unroll
        for (int k16 = 0; k16 < 2; k16++) {
            uint32_t Bh[8];
#pragma unroll
            for (int t = 0; t < 2; t++) {
                int sub = lane >> 3, r7 = lane & 7;
                uint32_t prow = wpx * 32 + (2 * t + (sub >> 1)) * 8 + r7;
                ldsm4(&Bh[4 * t], b + 10240 + prow * 80 + k16 * 32 + (sub & 1) * 16);
            }
#pragma unroll
            for (int mt = 0; mt < 4; mt++) {
                uint32_t Ah[4];
                uint32_t mrow = wco * 64 + mt * 16 + (lane & 15);
                ldsm4(Ah, b + mrow * 80 + k16 * 32 + (lane >> 4) * 16);
#pragma unroll
                for (int nt = 0; nt < 4; nt++)
                    mma16816(acc + mt * 16 + nt * 4, Ah, &Bh[2 * nt]);
            }
        }
        __syncthreads();
    }

    // ---- two-round epilogue: 64 px at a time through smem ----
    float* sT = (float*)smem;
    for (int rr = 0; rr < 2; rr++) {
        if ((wpx >> 1) == rr) {
            int cbase = (wpx & 1) * 32;
#pragma unroll
            for (int mt = 0; mt < 4; mt++)
#pragma unroll
                for (int nt = 0; nt < 4; nt++)
#pragma unroll
                    for (int r = 0; r < 4; r++) {
                        int row = wco * 64 + mt * 16 + (lane >> 2) + ((r >> 1) << 3);
                        int col = cbase + nt * 8 + ((lane & 3) << 1) + (r & 1);
                        sT[col * 132 + row] = acc[mt * 16 + nt * 4 + r];
                    }
        }
        __syncthreads();
        int lpx = tid >> 2, qtr = tid & 3;
        int px = rr * 64 + lpx;
        long srow = (long)n * SS + pxb + px;
        float* sRow = sT + lpx * 132 + qtr * 32;
        int cg0 = co0 + qtr * 32;
        if (mode == 0) {
            float* dst = outF + srow * cout + cg0;
#pragma unroll
            for (int j = 0; j < 32; j += 4)
                *(float4*)&dst[j] = *(const float4*)&sRow[j];
        } else if (mode == 1) {
            long ob = srow * CC + cg0;
#pragma unroll
            for (int j = 0; j < 32; j += 4) {
                float4 v = *(const float4*)&sRow[j];
                float4 cv = *(const float4*)&cvec[n * CC + cg0 + j];
                *(uint2*)(out16 + ob + j) =
                    make_uint2(packf(mp_silu(v.x * cv.x), mp_silu(v.y * cv.y)),
                               packf(mp_silu(v.z * cv.z), mp_silu(v.w * cv.w)));
            }
        } else if (mode == 2) {
            long ob = srow * CC + cg0;
#pragma unroll
            for (int j = 0; j < 32; j += 4) {
                float4 v = *(const float4*)&sRow[j];
                float4 r4 = *(const float4*)&res[ob + j];
                v.x = CA * r4.x + CB * v.x; v.y = CA * r4.y + CB * v.y;
                v.z = CA * r4.z + CB * v.z; v.w = CA * r4.w + CB * v.w;
                *(float4*)&outF[ob + j] = v;
                *(uint2*)(out16 + ob + j) = make_uint2(packf(v.x, v.y), packf(v.z, v.w));
            }
        } else if (mode == 3) {
            // fused qkv head-channel norm; 64-ch group = qtr pair
            float sum = 0.f;
#pragma unroll
            for (int j = 0; j < 32; j++) sum += sRow[j] * sRow[j];
            sum += __shfl_xor_sync(0xffffffffu, sum, 1);
            float scale = 1.f / (EPSV + sqrtf(sum) * 0.125f);
            int g64 = (cg0 >> 6);            // 0..11 = h*3+which
            int h = g64 / 3, which = g64 - h * 3;
            fp16* dst = (which == 0) ? g_q16 : (which == 1) ? g_k16 : g_v16;
            long ob = ((long)(n * NHEAD + h) * SS + pxb + px) * 64 + (qtr & 1) * 32;
#pragma unroll
            for (int j = 0; j < 32; j += 2)
                *(uint32_t*)(dst + ob + j) = packf(sRow[j] * scale, sRow[j + 1] * scale);
        } else {
            long ob = srow * CC + cg0;
#pragma unroll
            for (int j = 0; j < 32; j += 4) {
                float4 v = *(const float4*)&sRow[j];
                float4 r4 = *(const float4*)&res[ob + j];
                v.x = fminf(fmaxf(CA * r4.x + CB * v.x, -256.f), 256.f);
                v.y = fminf(fmaxf(CA * r4.y + CB * v.y, -256.f), 256.f);
                v.z = fminf(fmaxf(CA * r4.z + CB * v.z, -256.f), 256.f);
                v.w = fminf(fmaxf(CA * r4.w + CB * v.w, -256.f), 256.f);
                *(float4*)&sRow[j] = v;
            }
            __syncthreads();
            int co = tid >> 1, hp = tid & 1;
            float* op = outF + ((long)n * CC + co0 + co) * SS + pxb + rr * 64 + hp * 32;
#pragma unroll
            for (int j = 0; j < 32; j += 4) {
                float4 v;
                v.x = sT[(hp * 32 + j + 0) * 132 + co];
                v.y = sT[(hp * 32 + j + 1) * 132 + co];
                v.z = sT[(hp * 32 + j + 2) * 132 + co];
                v.w = sT[(hp * 32 + j + 3) * 132 + co];
                *(float4*)&op[j] = v;
            }
        }
        __syncthreads();
    }
}

// ---------------- fp16 MMA flash attention ----------------
#define ATT_SMEM (2 * 18432)
__global__ __launch_bounds__(256, 2) void k_fattn() {
    extern __shared__ char smem[];
    const int tid = threadIdx.x, lane = tid & 31, wid = tid >> 5;
    const int nh = blockIdx.y, qb = blockIdx.x * 128;
    const int n = nh >> 2, h = nh & 3;
    const uint32_t sb = smem_u32(smem);
    const long nhb = (long)nh * SS * 64;
    const fp16* kp = g_k16 + nhb;
    const fp16* vp = g_v16 + nhb;

    // ---- stage Q, build fragments ----
    {
        const fp16* qp = g_q16 + nhb + (long)qb * 64;
        for (int i = tid; i < 512; i += 256) {
            int r = i >> 2, seg = i & 3;
            cpa16(sb + r * 144 + seg * 32 + ((i & 4) ? 16 : 16) - 16 + (seg & 0) , qp, 0); // placeholder avoided
        }
    }
    // (re-do staging cleanly)
    {
        const fp16* qp = g_q16 + nhb + (long)qb * 64;
        for (int i = tid; i < 1024; i += 256) {
            int r = i >> 3, seg = i & 7;
            cpa16(sb + r * 144 + seg * 16, qp + r * 64 + seg * 8, 16);
        }
        asm volatile("cp.async.commit_group;" ::: "memory");
        asm volatile("cp.async.wait_group 0;" ::: "memory");
        __syncthreads();
    }
    uint32_t qf[4][4];
    {
        int r = wid * 16 + (lane & 15);
        int halfk = lane >> 4;
#pragma unroll
        for (int kc = 0; kc < 4; kc++)
            ldsm4(qf[kc], sb + r * 144 + (kc * 16 + halfk * 8) * 2);
    }
    __syncthreads();

    auto load_kv = [&](int t, int buf) {
        uint32_t b = sb + buf * 18432;
#pragma unroll
        for (int rep = 0; rep < 2; rep++) {
            int i = tid + rep * 256;
            int r = i >> 3, seg = i & 7;
            long off = ((long)t * 64 + r) * 64 + seg * 8;
            uint32_t d = b + r * 144 + seg * 16;
            cpa16(d, kp + off, 16);
            cpa16(d + 9216, vp + off, 16);
        }
        asm volatile("cp.async.commit_group;" ::: "memory");
    };

    float m0 = -1e30f, m1 = -1e30f, l0 = 0.f, l1 = 0.f;
    float acc[8][4];
#pragma unroll
    for (int j = 0; j < 8; j++)
#pragma unroll
        for (int i = 0; i < 4; i++) acc[j][i] = 0.f;

    load_kv(0, 0);
    for (int t = 0; t < 16; t++) {
        int buf = t & 1;
        if (t + 1 < 16) {
            load_kv(t + 1, buf ^ 1);
            asm volatile("cp.async.wait_group 1;" ::: "memory");
        } else {
            asm volatile("cp.async.wait_group 0;" ::: "memory");
        }
        __syncthreads();
        uint32_t kb = sb + buf * 18432;

        float sc[8][4];
#pragma unroll
        for (int j = 0; j < 8; j++)
#pragma unroll
            for (int i = 0; i < 4; i++) sc[j][i] = 0.f;
        const int g = lane >> 3, r7 = lane & 7;
#pragma unroll
        for (int ntp = 0; ntp < 4; ntp++) {
#pragma unroll
            for (int kc = 0; kc < 4; kc++) {
                uint32_t bh[4];
                ldsm4(bh, kb + (ntp * 16 + (g >> 1) * 8 + r7) * 144
                          + (kc * 16 + (g & 1) * 8) * 2);
                mma16816(sc[2 * ntp], qf[kc], bh);
                mma16816(sc[2 * ntp + 1], qf[kc], bh + 2);
            }
        }
        float mx0 = -1e30f, mx1 = -1e30f;
#pragma unroll
        for (int j = 0; j < 8; j++) {
#pragma unroll
            for (int i = 0; i < 4; i++) sc[j][i] *= 0.125f;
            mx0 = fmaxf(mx0, fmaxf(sc[j][0], sc[j][1]));
            mx1 = fmaxf(mx1, fmaxf(sc[j][2], sc[j][3]));
        }
        mx0 = fmaxf(mx0, __shfl_xor_sync(0xffffffffu, mx0, 1));
        mx0 = fmaxf(mx0, __shfl_xor_sync(0xffffffffu, mx0, 2));
        mx1 = fmaxf(mx1, __shfl_xor_sync(0xffffffffu, mx1, 1));
        mx1 = fmaxf(mx1, __shfl_xor_sync(0xffffffffu, mx1, 2));
        float nm0 = fmaxf(m0, mx0), nm1 = fmaxf(m1, mx1);
        float f0 = __expf(m0 - nm0), f1 = __expf(m1 - nm1);
        m0 = nm0; m1 = nm1;
        l0 *= f0; l1 *= f1;
#pragma unroll
        for (int j = 0; j < 8; j++) {
            sc[j][0] = __expf(sc[j][0] - nm0);
            sc[j][1] = __expf(sc[j][1] - nm0);
            sc[j][2] = __expf(sc[j][2] - nm1);
            sc[j][3] = __expf(sc[j][3] - nm1);
            l0 += sc[j][0] + sc[j][1];
            l1 += sc[j][2] + sc[j][3];
        }
#pragma unroll
        for (int j = 0; j < 8; j++) {
            acc[j][0] *= f0; acc[j][1] *= f0;
            acc[j][2] *= f1; acc[j][3] *= f1;
        }
#pragma unroll
        for (int kk = 0; kk < 4; kk++) {
            uint32_t ph[4];
#pragma unroll
            for (int half = 0; half < 2; half++) {
                int j = 2 * kk + half;
                ph[2 * half]     = packf(sc[j][0], sc[j][1]);
                ph[2 * half + 1] = packf(sc[j][2], sc[j][3]);
            }
#pragma unroll
            for (int ctp = 0; ctp < 4; ctp++) {
                uint32_t vh4[4];
                ldsm4t(vh4, kb + 9216 + (kk * 16 + (g & 1) * 8 + r7) * 144
                            + (ctp * 16 + (g >> 1) * 8) * 2);
                mma16816(acc[2 * ctp], ph, vh4);
                mma16816(acc[2 * ctp + 1], ph, vh4 + 2);
            }
        }
        __syncthreads();
    }

    l0 += __shfl_xor_sync(0xffffffffu, l0, 1);
    l0 += __shfl_xor_sync(0xffffffffu, l0, 2);
    l1 += __shfl_xor_sync(0xffffffffu, l1, 1);
    l1 += __shfl_xor_sync(0xffffffffu, l1, 2);
    float i0 = 1.f / l0, i1 = 1.f / l1;
    int t4 = lane & 3;
    int s0r = qb + wid * 16 + (lane >> 2);
    long b0 = ((long)n * SS + s0r) * CC + h * 64;
    long b1 = ((long)n * SS + s0r + 8) * CC + h * 64;
#pragma unroll
    for (int j = 0; j < 8; j++) {
        int ch = j * 8 + t4 * 2;
        *(uint32_t*)(g_b16 + b0 + ch) = packf(acc[j][0] * i0, acc[j][1] * i0);
        *(uint32_t*)(g_b16 + b1 + ch) = packf(acc[j][2] * i1, acc[j][3] * i1);
    }
}

// ---------------- launcher ----------------
extern "C" void kernel_launch(void* const* d_in, const int* in_sizes, int n_in,
                              void* d_out, int out_size) {
    const float* x      = (const float*)d_in[0];
    const float* emb    = (const float*)d_in[1];
    const float* w_skip = (const float*)d_in[2];
    const float* w_res0 = (const float*)d_in[3];
    const float* w_res1 = (const float*)d_in[4];
    const float* w_emb  = (const float*)d_in[5];
    const float* emb_g  = (const float*)d_in[6];
    const float* w_qkv  = (const float*)d_in[7];
    const float* w_proj = (const float*)d_in[8];
    float* out = (float*)d_out;

    fp16 *p_a16, *p_b16, *pw_skip, *pw_res0, *pw_res1, *pw_qkv, *pw_proj;
    float *p_wemb, *p_x, *p_c;
    cudaGetSymbolAddress((void**)&p_a16, g_a16);
    cudaGetSymbolAddress((void**)&p_b16, g_b16);
    cudaGetSymbolAddress((void**)&pw_skip, g_w_skip);
    cudaGetSymbolAddress((void**)&pw_res0, g_w_res0);
    cudaGetSymbolAddress((void**)&pw_res1, g_w_res1);
    cudaGetSymbolAddress((void**)&pw_qkv, g_w_qkv);
    cudaGetSymbolAddress((void**)&pw_proj, g_w_proj);
    cudaGetSymbolAddress((void**)&p_wemb, g_wemb);
    cudaGetSymbolAddress((void**)&p_x, g_x);
    cudaGetSymbolAddress((void**)&p_c, g_c);

    cudaFuncSetAttribute(k_gemm, cudaFuncAttributeMaxDynamicSharedMemorySize, GSMEM);
    cudaFuncSetAttribute(k_fattn, cudaFuncAttributeMaxDynamicSharedMemorySize, ATT_SMEM);

    // weight prep
    k_wprep<<<CC, 256>>>(w_skip, pw_skip, CIN, 1, 0);
    k_wprep<<<CC, 256>>>(w_res0, pw_res0, CC, 9, 0);
    k_wprep<<<CC, 256>>>(w_res1, pw_res1, CC, 9, 0);
    k_wprep<<<3 * CC, 256>>>(w_qkv, pw_qkv, CC, 1, 1);
    k_wprep<<<CC, 256>>>(w_proj, pw_proj, CC, 1, 0);
    k_wnorm<<<CC, 256>>>(w_emb, p_wemb, CE, emb_g);
    k_emb<<<NB, 256>>>(emb);

    // input NCHW -> channel-last fp16
    k_split0<<<dim3(SS / 32, CIN / 32, NB), 256>>>(x);

    // skip conv (192->256) -> fp32 x
    k_gemm<<<dim3(8, 2, NB), 256, GSMEM>>>(p_a16, pw_skip, p_x, nullptr,
                                           nullptr, nullptr, CIN, CC, 1, 0);
    // pixel norm + silu -> a16
    k_pixnorm<<<NB * SS / 8, 256>>>(p_x);
    // res0: silu(conv3x3 * c) -> b16
    k_gemm<<<dim3(8, 2, NB), 256, GSMEM>>>(p_a16, pw_res0, nullptr, p_b16,
                                           nullptr, p_c, CC, CC, 9, 1);
    // res1: x = CA*x + CB*conv3x3 -> fp32 x + a16
    k_gemm<<<dim3(8, 2, NB), 256, GSMEM>>>(p_b16, pw_res1, p_x, p_a16,
                                           p_x, nullptr, CC, CC, 9, 2);
    // qkv conv (256->768) + fused head-channel norm -> q/k/v fp16
    k_gemm<<<dim3(8, 6, NB), 256, GSMEM>>>(p_a16, pw_qkv, nullptr, nullptr,
                                           nullptr, nullptr, CC, 3 * CC, 1, 3);
    // fp16 MMA flash attention -> b16
    k_fattn<<<dim3(SS / 128, NB * NHEAD), 256, ATT_SMEM>>>();
    // proj + mp_sum + clip -> d_out (NCHW)
    k_gemm<<<dim3(8, 2, NB), 256, GSMEM>>>(p_b16, pw_proj, out, nullptr,
                                           p_x, nullptr, CC, CC, 1, 4);
}